// round 1
// baseline (speedup 1.0000x reference)
#include <cuda_runtime.h>
#include <math.h>

// Problem constants
#define BI   4
#define LSEQ 2048
#define DM   512
#define DI   1024      // d_inner
#define DS   16        // d_state
#define DTR  32        // dt_rank
#define NR   (BI*LSEQ) // 8192 rows (b*L flattened)

// ---------------- scratch (static device globals; no allocation) ----------------
__device__ float g_xz  [NR * 2 * DI];   // [row][2048]  x = [:1024], z = [1024:]
__device__ float g_xc  [2][NR * DI];    // conv+silu output per direction (dir-local time)
__device__ float g_xdbl[2][NR * 64];    // [row][64]: dt_r[0:32], B[32:48], C[48:64]
__device__ float g_dt  [2][NR * DI];    // softplus(dt) per direction
__device__ float g_y   [2][NR * DI];    // scan output per direction (dir-local time)
__device__ float g_ysum[NR * DI];       // y_fwd + reverse(y_rev)

// ---------------- generic fp32 tiled GEMM:  C[M,N] = A[M,K] @ W[N,K]^T ----------------
// BM=BN=64, BK=16, 256 threads, 4x4 microtile.
// EPI 0: plain store.  EPI 1: softplus(acc + bias[col]).
template <int EPI>
__global__ void __launch_bounds__(256)
gemm_nt(const float* __restrict__ A, int lda,
        const float* __restrict__ W,
        float* __restrict__ C,
        int M, int N, int K,
        const float* __restrict__ bias)
{
    const int BM = 64, BN = 64, BK = 16;
    __shared__ float As[BK][BM];
    __shared__ float Ws[BK][BN];

    int tid = threadIdx.x;
    int tx = tid % 16, ty = tid / 16;
    int rowBase = blockIdx.y * BM;
    int colBase = blockIdx.x * BN;

    int lr = tid / 4;          // 0..63 : row within tile
    int lk = (tid % 4) * 4;    // 0,4,8,12 : k offset (float4)

    float acc[4][4];
#pragma unroll
    for (int i = 0; i < 4; i++)
#pragma unroll
        for (int j = 0; j < 4; j++) acc[i][j] = 0.f;

    for (int k0 = 0; k0 < K; k0 += BK) {
        float4 av = *(const float4*)&A[(size_t)(rowBase + lr) * lda + k0 + lk];
        float4 wv = *(const float4*)&W[(size_t)(colBase + lr) * K   + k0 + lk];
        __syncthreads();
        As[lk + 0][lr] = av.x; As[lk + 1][lr] = av.y;
        As[lk + 2][lr] = av.z; As[lk + 3][lr] = av.w;
        Ws[lk + 0][lr] = wv.x; Ws[lk + 1][lr] = wv.y;
        Ws[lk + 2][lr] = wv.z; Ws[lk + 3][lr] = wv.w;
        __syncthreads();
#pragma unroll
        for (int k = 0; k < BK; k++) {
            float4 a = *(const float4*)&As[k][ty * 4];
            float4 b = *(const float4*)&Ws[k][tx * 4];
            acc[0][0] += a.x * b.x; acc[0][1] += a.x * b.y; acc[0][2] += a.x * b.z; acc[0][3] += a.x * b.w;
            acc[1][0] += a.y * b.x; acc[1][1] += a.y * b.y; acc[1][2] += a.y * b.z; acc[1][3] += a.y * b.w;
            acc[2][0] += a.z * b.x; acc[2][1] += a.z * b.y; acc[2][2] += a.z * b.z; acc[2][3] += a.z * b.w;
            acc[3][0] += a.w * b.x; acc[3][1] += a.w * b.y; acc[3][2] += a.w * b.z; acc[3][3] += a.w * b.w;
        }
    }

#pragma unroll
    for (int i = 0; i < 4; i++) {
        int row = rowBase + ty * 4 + i;
        float4 v;
        float* pv = &v.x;
#pragma unroll
        for (int j = 0; j < 4; j++) {
            float t = acc[i][j];
            if (EPI == 1) {
                int col = colBase + tx * 4 + j;
                t += bias[col];
                t = (t > 20.f) ? t : log1pf(expf(t));  // softplus
            }
            pv[j] = t;
        }
        *(float4*)&C[(size_t)row * N + colBase + tx * 4] = v;
    }
}

// ---------------- depthwise causal conv (K=4) + SiLU, both directions ----------------
__global__ void conv_silu_kernel(const float* __restrict__ cw_f, const float* __restrict__ cb_f,
                                 const float* __restrict__ cw_r, const float* __restrict__ cb_r)
{
    int idx = blockIdx.x * blockDim.x + threadIdx.x;
    if (idx >= 2 * NR * DI) return;
    int d   = idx % DI;
    int r   = (idx / DI) % NR;
    int dir = idx / (DI * NR);
    int b = r / LSEQ, t = r % LSEQ;

    const float* cw = dir ? cw_r : cw_f;
    const float* cb = dir ? cb_r : cb_f;

    float accv = cb[d];
#pragma unroll
    for (int k = 0; k < 4; k++) {
        int tt = t - 3 + k;
        if (tt >= 0) {
            int ts = dir ? (LSEQ - 1 - tt) : tt;
            accv += cw[d * 4 + k] * g_xz[(size_t)(b * LSEQ + ts) * (2 * DI) + d];
        }
    }
    // silu
    float s = accv / (1.f + __expf(-accv));
    g_xc[dir][(size_t)r * DI + d] = s;
}

// ---------------- selective scan: warp = 2 channels x 16 states ----------------
__global__ void __launch_bounds__(256)
scan_kernel(const float* __restrict__ Alog_f, const float* __restrict__ D_f,
            const float* __restrict__ Alog_r, const float* __restrict__ D_r)
{
    int w    = (blockIdx.x * blockDim.x + threadIdx.x) / 32;  // 0..4095
    int lane = threadIdx.x % 32;
    int c = lane / 16;      // channel within warp (0/1)
    int n = lane % 16;      // state index

    int dir = w / 2048;
    int rem = w % 2048;
    int b   = rem / 512;
    int d   = (rem % 512) * 2 + c;

    const float* Alog = dir ? Alog_r : Alog_f;
    const float* Dp   = dir ? D_r   : D_f;

    float Av = -expf(Alog[d * DS + n]);
    float Dd = Dp[d];

    const float* dtp = &g_dt[dir][(size_t)(b * LSEQ) * DI + d];
    const float* xp  = &g_xc[dir][(size_t)(b * LSEQ) * DI + d];
    const float* bp  = &g_xdbl[dir][(size_t)(b * LSEQ) * 64 + DTR + n];
    const float* cp  = bp + DS;
    float*       yp  = &g_y[dir][(size_t)(b * LSEQ) * DI + d];

    float h = 0.f;
    for (int t = 0; t < LSEQ; t++) {
        float dtv = dtp[(size_t)t * DI];
        float xv  = xp [(size_t)t * DI];
        float Bv  = bp [(size_t)t * 64];
        float Cv  = cp [(size_t)t * 64];

        float dA = __expf(dtv * Av);
        h = dA * h + (dtv * xv) * Bv;

        float p = h * Cv;
        p += __shfl_xor_sync(0xffffffffu, p, 8);
        p += __shfl_xor_sync(0xffffffffu, p, 4);
        p += __shfl_xor_sync(0xffffffffu, p, 2);
        p += __shfl_xor_sync(0xffffffffu, p, 1);

        if (n == 0) {
            int torig = dir ? (LSEQ - 1 - t) : t;
            float zv = g_xz[(size_t)(b * LSEQ + torig) * (2 * DI) + DI + d];
            float y  = p + Dd * xv;
            float zs = zv / (1.f + __expf(-zv));
            yp[(size_t)t * DI] = y * zs;
        }
    }
}

// ---------------- combine: ysum[b,t,d] = y_fwd[b,t,d] + y_rev[b,L-1-t,d] ----------------
__global__ void combine_kernel()
{
    int idx = blockIdx.x * blockDim.x + threadIdx.x;
    if (idx >= NR * DI) return;
    int d = idx % DI;
    int r = idx / DI;
    int b = r / LSEQ, t = r % LSEQ;
    int rr = b * LSEQ + (LSEQ - 1 - t);
    g_ysum[idx] = g_y[0][idx] + g_y[1][(size_t)rr * DI + d];
}

// ---------------- launch ----------------
extern "C" void kernel_launch(void* const* d_in, const int* in_sizes, int n_in,
                              void* d_out, int out_size)
{
    const float* hidden = (const float*)d_in[0];
    const float* W_in   = (const float*)d_in[1];
    const float* W_out  = (const float*)d_in[2];
    const float* cw_f   = (const float*)d_in[3];
    const float* cb_f   = (const float*)d_in[4];
    const float* Wx_f   = (const float*)d_in[5];
    const float* Wdt_f  = (const float*)d_in[6];
    const float* bdt_f  = (const float*)d_in[7];
    const float* Alog_f = (const float*)d_in[8];
    const float* D_f    = (const float*)d_in[9];
    const float* cw_r   = (const float*)d_in[10];
    const float* cb_r   = (const float*)d_in[11];
    const float* Wx_r   = (const float*)d_in[12];
    const float* Wdt_r  = (const float*)d_in[13];
    const float* bdt_r  = (const float*)d_in[14];
    const float* Alog_r = (const float*)d_in[15];
    const float* D_r    = (const float*)d_in[16];
    float* out = (float*)d_out;

    float* xz; cudaGetSymbolAddress((void**)&xz, g_xz);
    float* xc; cudaGetSymbolAddress((void**)&xc, g_xc);
    float* xdbl; cudaGetSymbolAddress((void**)&xdbl, g_xdbl);
    float* dtb; cudaGetSymbolAddress((void**)&dtb, g_dt);
    float* ysum; cudaGetSymbolAddress((void**)&ysum, g_ysum);

    // 1) xz = hidden @ W_in^T   [8192,512] x [2048,512]^T -> [8192,2048]
    {
        dim3 grid(2 * DI / 64, NR / 64);
        gemm_nt<0><<<grid, 256>>>(hidden, DM, W_in, xz, NR, 2 * DI, DM, nullptr);
    }

    // 2) conv + silu (both dirs)
    {
        int total = 2 * NR * DI;
        conv_silu_kernel<<<(total + 255) / 256, 256>>>(cw_f, cb_f, cw_r, cb_r);
    }

    // 3) x_dbl = xc @ W_x^T  [8192,1024] x [64,1024]^T -> [8192,64]  (per dir)
    {
        dim3 grid(64 / 64, NR / 64);
        gemm_nt<0><<<grid, 256>>>(xc,           DI, Wx_f, xdbl,           NR, 64, DI, nullptr);
        gemm_nt<0><<<grid, 256>>>(xc + (size_t)NR * DI, DI, Wx_r, xdbl + (size_t)NR * 64, NR, 64, DI, nullptr);
    }

    // 4) dt = softplus(dt_r @ W_dt^T + b_dt)  [8192,32] x [1024,32]^T -> [8192,1024]
    {
        dim3 grid(DI / 64, NR / 64);
        gemm_nt<1><<<grid, 256>>>(xdbl,           64, Wdt_f, dtb,           NR, DI, DTR, bdt_f);
        gemm_nt<1><<<grid, 256>>>(xdbl + (size_t)NR * 64, 64, Wdt_r, dtb + (size_t)NR * DI, NR, DI, DTR, bdt_r);
    }

    // 5) selective scan (both dirs)
    {
        // 4096 warps total, 8 warps/block -> 512 blocks
        scan_kernel<<<512, 256>>>(Alog_f, D_f, Alog_r, D_r);
    }

    // 6) combine y_fwd + reverse(y_rev)
    {
        int total = NR * DI;
        combine_kernel<<<(total + 255) / 256, 256>>>();
    }

    // 7) out = ysum @ W_out^T  [8192,1024] x [512,1024]^T -> [8192,512]
    {
        dim3 grid(DM / 64, NR / 64);
        gemm_nt<0><<<grid, 256>>>(ysum, DI, W_out, out, NR, DM, DI, nullptr);
    }
}

// round 2
// speedup vs baseline: 1.6681x; 1.6681x over previous
#include <cuda_runtime.h>
#include <math.h>

// Problem constants
#define BI   4
#define LSEQ 2048
#define DM   512
#define DI   1024      // d_inner
#define DS   16        // d_state
#define DTR  32        // dt_rank
#define NR   (BI*LSEQ) // 8192 rows (b*L flattened)

// ---------------- scratch (static device globals; no allocation) ----------------
__device__ float g_xz  [NR * 2 * DI];   // [row][2048]  x = [:1024], z = [1024:]
__device__ float g_xc  [2][NR * DI];    // conv+silu output per direction (dir-local time)
__device__ float g_xdbl[2][NR * 64];    // [row][64]: dt_r[0:32], B[32:48], C[48:64]
__device__ float g_dt  [2][NR * DI];    // softplus(dt) per direction
__device__ float g_y   [2][NR * DI];    // scan output per direction (dir-local time)

// ==================================================================================
// Tiled fp32 GEMM:  C[M,N] = A[M,K] @ W[N,K]^T
// BM x BN block tile, BK=16, 256 threads, TM x TN microtile, double-buffered smem.
// EPI  : 0 = plain store, 1 = softplus(acc + bias[col])
// FUSEA: 1 = A element is A[r] + A2[r ^ 2047]  (y_fwd + time-reversed y_rev)
// ==================================================================================
template <int BM, int BN, int TM, int TN, int EPI, int FUSEA>
__global__ void __launch_bounds__(256, 1)
gemm_nt(const float* __restrict__ A, const float* __restrict__ A2, int lda,
        const float* __restrict__ W,
        float* __restrict__ C,
        int M, int N, int K,
        const float* __restrict__ bias)
{
    constexpr int BK = 16;
    constexpr int AV = (BM * BK) / (256 * 4);  // float4 loads per thread for A tile
    constexpr int WV = (BN * BK) / (256 * 4);  // float4 loads per thread for W tile

    __shared__ float As[2][BK][BM];
    __shared__ float Ws[2][BK][BN];

    const int tid = threadIdx.x;
    const int tx  = tid & 15;      // 0..15 (col group)
    const int ty  = tid >> 4;      // 0..15 (row group)
    const int rowBase = blockIdx.y * BM;
    const int colBase = blockIdx.x * BN;

    const int lr = tid >> 2;          // 0..63
    const int lk = (tid & 3) * 4;     // 0,4,8,12

    float4 pa[AV];
    float4 pw[WV];

    // ---- load one k-tile from global into regs ----
    auto load_g = [&](int k0) {
#pragma unroll
        for (int i = 0; i < AV; i++) {
            int r = rowBase + lr + 64 * i;
            float4 v = *(const float4*)&A[(size_t)r * lda + k0 + lk];
            if (FUSEA) {
                int rr = r ^ 2047;
                float4 v2 = *(const float4*)&A2[(size_t)rr * lda + k0 + lk];
                v.x += v2.x; v.y += v2.y; v.z += v2.z; v.w += v2.w;
            }
            pa[i] = v;
        }
#pragma unroll
        for (int i = 0; i < WV; i++) {
            int r = colBase + lr + 64 * i;
            pw[i] = *(const float4*)&W[(size_t)r * K + k0 + lk];
        }
    };

    // ---- store staged regs into smem buffer `buf` (transposed) ----
    auto store_s = [&](int buf) {
#pragma unroll
        for (int i = 0; i < AV; i++) {
            int r = lr + 64 * i;
            As[buf][lk + 0][r] = pa[i].x;
            As[buf][lk + 1][r] = pa[i].y;
            As[buf][lk + 2][r] = pa[i].z;
            As[buf][lk + 3][r] = pa[i].w;
        }
#pragma unroll
        for (int i = 0; i < WV; i++) {
            int r = lr + 64 * i;
            Ws[buf][lk + 0][r] = pw[i].x;
            Ws[buf][lk + 1][r] = pw[i].y;
            Ws[buf][lk + 2][r] = pw[i].z;
            Ws[buf][lk + 3][r] = pw[i].w;
        }
    };

    float acc[TM][TN];
#pragma unroll
    for (int i = 0; i < TM; i++)
#pragma unroll
        for (int j = 0; j < TN; j++) acc[i][j] = 0.f;

    load_g(0);
    store_s(0);
    __syncthreads();

    int cur = 0;
    for (int k0 = 0; k0 < K; k0 += BK) {
        const bool has_next = (k0 + BK < K);
        if (has_next) load_g(k0 + BK);

#pragma unroll
        for (int kk = 0; kk < BK; kk++) {
            float a[TM], b[TN];
#pragma unroll
            for (int i = 0; i < TM / 4; i++)
                *(float4*)&a[4 * i] = *(const float4*)&As[cur][kk][ty * TM + 4 * i];
#pragma unroll
            for (int j = 0; j < TN / 4; j++)
                *(float4*)&b[4 * j] = *(const float4*)&Ws[cur][kk][tx * TN + 4 * j];
#pragma unroll
            for (int i = 0; i < TM; i++)
#pragma unroll
                for (int j = 0; j < TN; j++)
                    acc[i][j] += a[i] * b[j];
        }

        if (has_next) {
            store_s(cur ^ 1);
            __syncthreads();
            cur ^= 1;
        }
    }

    // ---- epilogue ----
#pragma unroll
    for (int i = 0; i < TM; i++) {
        int row = rowBase + ty * TM + i;
#pragma unroll
        for (int j4 = 0; j4 < TN / 4; j4++) {
            float4 v;
            float* pv = &v.x;
#pragma unroll
            for (int j = 0; j < 4; j++) {
                int col = colBase + tx * TN + j4 * 4 + j;
                float t = acc[i][j4 * 4 + j];
                if (EPI == 1) {
                    t += bias[col];
                    t = (t > 20.f) ? t : log1pf(expf(t));  // softplus
                }
                pv[j] = t;
            }
            *(float4*)&C[(size_t)row * N + colBase + tx * TN + j4 * 4] = v;
        }
    }
}

// ---------------- depthwise causal conv (K=4) + SiLU, both directions ----------------
__global__ void conv_silu_kernel(const float* __restrict__ cw_f, const float* __restrict__ cb_f,
                                 const float* __restrict__ cw_r, const float* __restrict__ cb_r)
{
    int idx = blockIdx.x * blockDim.x + threadIdx.x;
    if (idx >= 2 * NR * DI) return;
    int d   = idx % DI;
    int r   = (idx / DI) % NR;
    int dir = idx / (DI * NR);
    int b = r / LSEQ, t = r % LSEQ;

    const float* cw = dir ? cw_r : cw_f;
    const float* cb = dir ? cb_r : cb_f;

    float accv = cb[d];
#pragma unroll
    for (int k = 0; k < 4; k++) {
        int tt = t - 3 + k;
        if (tt >= 0) {
            int ts = dir ? (LSEQ - 1 - tt) : tt;
            accv += cw[d * 4 + k] * g_xz[(size_t)(b * LSEQ + ts) * (2 * DI) + d];
        }
    }
    float s = accv / (1.f + __expf(-accv));
    g_xc[dir][(size_t)r * DI + d] = s;
}

// ---------------- selective scan: warp = 2 channels x 16 states, pipelined ----------------
__global__ void __launch_bounds__(256)
scan_kernel(const float* __restrict__ Alog_f, const float* __restrict__ D_f,
            const float* __restrict__ Alog_r, const float* __restrict__ D_r)
{
    int w    = (blockIdx.x * blockDim.x + threadIdx.x) / 32;  // 0..4095
    int lane = threadIdx.x % 32;
    int c = lane / 16;      // channel within warp (0/1)
    int n = lane % 16;      // state index

    int dir = w / 2048;
    int rem = w % 2048;
    int b   = rem / 512;
    int d   = (rem % 512) * 2 + c;

    const float* Alog = dir ? Alog_r : Alog_f;
    const float* Dp   = dir ? D_r   : D_f;

    const float Av = -expf(Alog[d * DS + n]);
    const float Dd = Dp[d];

    const float* dtp = &g_dt[dir][(size_t)(b * LSEQ) * DI + d];
    const float* xp  = &g_xc[dir][(size_t)(b * LSEQ) * DI + d];
    const float* bp  = &g_xdbl[dir][(size_t)(b * LSEQ) * 64 + DTR + n];
    const float* cp  = bp + DS;
    float*       yp  = &g_y[dir][(size_t)(b * LSEQ) * DI + d];

    // z pointer walks original time order (reversed for dir 1)
    const float* zp = &g_xz[(size_t)(b * LSEQ + (dir ? LSEQ - 1 : 0)) * (2 * DI) + DI + d];
    const long  zstep = dir ? -(long)(2 * DI) : (long)(2 * DI);

    float h = 0.f;

    float dtv = dtp[0];
    float xv  = xp[0];
    float Bv  = bp[0];
    float Cv  = cp[0];

    auto step = [&](int t, float dt_c, float x_c, float B_c, float C_c) {
        float dA = __expf(dt_c * Av);
        h = dA * h + (dt_c * x_c) * B_c;

        float p = h * C_c;
        p += __shfl_xor_sync(0xffffffffu, p, 8);
        p += __shfl_xor_sync(0xffffffffu, p, 4);
        p += __shfl_xor_sync(0xffffffffu, p, 2);
        p += __shfl_xor_sync(0xffffffffu, p, 1);

        if (n == 0) {
            float zv = *zp;
            float y  = p + Dd * x_c;
            float zs = zv / (1.f + __expf(-zv));
            yp[(size_t)t * DI] = y * zs;
        }
        zp += zstep;
    };

#pragma unroll 2
    for (int t = 0; t < LSEQ - 1; t++) {
        // prefetch next step's operands before the dependent chain
        float dtn = dtp[(size_t)(t + 1) * DI];
        float xn  = xp [(size_t)(t + 1) * DI];
        float Bn  = bp [(size_t)(t + 1) * 64];
        float Cn  = cp [(size_t)(t + 1) * 64];

        step(t, dtv, xv, Bv, Cv);

        dtv = dtn; xv = xn; Bv = Bn; Cv = Cn;
    }
    step(LSEQ - 1, dtv, xv, Bv, Cv);
}

// ---------------- launch ----------------
extern "C" void kernel_launch(void* const* d_in, const int* in_sizes, int n_in,
                              void* d_out, int out_size)
{
    const float* hidden = (const float*)d_in[0];
    const float* W_in   = (const float*)d_in[1];
    const float* W_out  = (const float*)d_in[2];
    const float* cw_f   = (const float*)d_in[3];
    const float* cb_f   = (const float*)d_in[4];
    const float* Wx_f   = (const float*)d_in[5];
    const float* Wdt_f  = (const float*)d_in[6];
    const float* bdt_f  = (const float*)d_in[7];
    const float* Alog_f = (const float*)d_in[8];
    const float* D_f    = (const float*)d_in[9];
    const float* cw_r   = (const float*)d_in[10];
    const float* cb_r   = (const float*)d_in[11];
    const float* Wx_r   = (const float*)d_in[12];
    const float* Wdt_r  = (const float*)d_in[13];
    const float* bdt_r  = (const float*)d_in[14];
    const float* Alog_r = (const float*)d_in[15];
    const float* D_r    = (const float*)d_in[16];
    float* out = (float*)d_out;

    float* xz;   cudaGetSymbolAddress((void**)&xz,   g_xz);
    float* xc;   cudaGetSymbolAddress((void**)&xc,   g_xc);
    float* xdbl; cudaGetSymbolAddress((void**)&xdbl, g_xdbl);
    float* dtb;  cudaGetSymbolAddress((void**)&dtb,  g_dt);
    float* yb;   cudaGetSymbolAddress((void**)&yb,   g_y);

    // 1) xz = hidden @ W_in^T   [8192,512] x [2048,512]^T -> [8192,2048]
    {
        dim3 grid((2 * DI) / 128, NR / 128);
        gemm_nt<128, 128, 8, 8, 0, 0><<<grid, 256>>>(hidden, nullptr, DM, W_in, xz,
                                                     NR, 2 * DI, DM, nullptr);
    }

    // 2) conv + silu (both dirs)
    {
        int total = 2 * NR * DI;
        conv_silu_kernel<<<(total + 255) / 256, 256>>>(cw_f, cb_f, cw_r, cb_r);
    }

    // 3) x_dbl = xc @ W_x^T  [8192,1024] x [64,1024]^T -> [8192,64]  (per dir)
    {
        dim3 grid(64 / 64, NR / 128);
        gemm_nt<128, 64, 8, 4, 0, 0><<<grid, 256>>>(xc, nullptr, DI, Wx_f, xdbl,
                                                    NR, 64, DI, nullptr);
        gemm_nt<128, 64, 8, 4, 0, 0><<<grid, 256>>>(xc + (size_t)NR * DI, nullptr, DI, Wx_r,
                                                    xdbl + (size_t)NR * 64, NR, 64, DI, nullptr);
    }

    // 4) dt = softplus(dt_r @ W_dt^T + b_dt)  [8192,32] x [1024,32]^T -> [8192,1024]
    {
        dim3 grid(DI / 128, NR / 128);
        gemm_nt<128, 128, 8, 8, 1, 0><<<grid, 256>>>(xdbl, nullptr, 64, Wdt_f, dtb,
                                                     NR, DI, DTR, bdt_f);
        gemm_nt<128, 128, 8, 8, 1, 0><<<grid, 256>>>(xdbl + (size_t)NR * 64, nullptr, 64, Wdt_r,
                                                     dtb + (size_t)NR * DI, NR, DI, DTR, bdt_r);
    }

    // 5) selective scan (both dirs): 4096 warps
    scan_kernel<<<512, 256>>>(Alog_f, D_f, Alog_r, D_r);

    // 6+7) out = (y_fwd + reverse(y_rev)) @ W_out^T  [8192,1024] x [512,1024]^T -> [8192,512]
    {
        dim3 grid(DM / 128, NR / 128);
        gemm_nt<128, 128, 8, 8, 0, 1><<<grid, 256>>>(yb, yb + (size_t)NR * DI, DI, W_out, out,
                                                     NR, DM, DI, nullptr);
    }
}

// round 4
// speedup vs baseline: 1.8413x; 1.1038x over previous
#include <cuda_runtime.h>
#include <math.h>
#include <stdint.h>

// Problem constants
#define BI   4
#define LSEQ 2048
#define DM   512
#define DI   1024      // d_inner
#define DS   16        // d_state
#define DTR  32        // dt_rank
#define NR   (BI*LSEQ) // 8192 rows (b*L flattened)

// ---------------- scratch (static device globals; no allocation) ----------------
__device__ float g_xz  [NR * 2 * DI];   // [row][2048]  x = [:1024], z = [1024:]
__device__ float g_xc  [2][NR * DI];    // conv+silu output per direction (dir-local time)
__device__ float g_xdbl[2][NR * 64];    // [row][64]: dt_r[0:32], B[32:48], C[48:64]
__device__ float g_dt  [2][NR * DI];    // softplus(dt) per direction
__device__ float g_y   [2][NR * DI];    // scan output per direction (dir-local time)

// ---------------- tf32 helpers ----------------
__device__ __forceinline__ uint32_t f2tf(float v) {
    uint32_t r; asm("cvt.rna.tf32.f32 %0, %1;" : "=r"(r) : "f"(v)); return r;
}

__device__ __forceinline__ void mma8(float4& d, const uint32_t* a, const uint32_t* b) {
    asm volatile("mma.sync.aligned.m16n8k8.row.col.f32.tf32.tf32.f32 "
                 "{%0,%1,%2,%3}, {%4,%5,%6,%7}, {%8,%9}, {%0,%1,%2,%3};"
                 : "+f"(d.x), "+f"(d.y), "+f"(d.z), "+f"(d.w)
                 : "r"(a[0]), "r"(a[1]), "r"(a[2]), "r"(a[3]), "r"(b[0]), "r"(b[1]));
}

__device__ __forceinline__ float softplus_f(float t) {
    return (t > 20.f) ? t : log1pf(expf(t));
}

// ==================================================================================
// Split-tf32 tensor-core GEMM:  C[M,N] = A[M,K] @ W[N,K]^T   (full fp32-grade accuracy)
// A = Ahi + Alo (tf32 split), same for W; acc += Ah*Wh + Ah*Wl + Al*Wh  (3 MMAs)
// BM x BN tile, BK=16, 256 threads (8 warps: 4 row-groups x 2 col-groups).
// EPI  : 0 = plain store, 1 = softplus(acc + bias[col])
// FUSEA: A element = A[r] + A2[r ^ 2047]   (y_fwd + time-reversed y_rev)
// blockIdx.z batching: A += z*sA, C += z*sC, W/bias selected by z.
// ==================================================================================
template <int BM, int BN, int EPI, int FUSEA>
__global__ void __launch_bounds__(256, 1)
gemm_tf32(const float* __restrict__ A, const float* __restrict__ A2, int lda,
          const float* __restrict__ W0, const float* __restrict__ W1,
          float* __restrict__ C, int M, int N, int K,
          const float* __restrict__ bias0, const float* __restrict__ bias1,
          long sA, long sC)
{
    constexpr int BK = 16;
    constexpr int SS = BK + 4;       // stride 20 floats: conflict-free frag LDS, 16B-aligned rows
    constexpr int AV = BM / 64;      // float4 global loads per thread (A)
    constexpr int WV = BN / 64;      // float4 global loads per thread (W)
    constexpr int NT = BN / 16;      // n-tiles (8 cols each) per warp

    __shared__ float Ah[BM][SS], Al[BM][SS];
    __shared__ float Wh[BN][SS], Wl[BN][SS];

    const float* W    = blockIdx.z ? W1    : W0;
    const float* bias = blockIdx.z ? bias1 : bias0;
    A += (long)blockIdx.z * sA;
    C += (long)blockIdx.z * sC;

    const int tid  = threadIdx.x;
    const int warp = tid >> 5, lane = tid & 31;
    const int wrow = warp & 3, wcol = warp >> 2;
    const int rowBase = blockIdx.y * BM;
    const int colBase = blockIdx.x * BN;
    const int lr = tid >> 2;           // 0..63
    const int lk = (tid & 3) * 4;      // 0,4,8,12
    const int qid = lane >> 2, tig = lane & 3;

    float4 pa[AV], pw[WV];

    auto load_g = [&](int k0) {
#pragma unroll
        for (int i = 0; i < AV; i++) {
            int r = rowBase + lr + 64 * i;
            float4 v = *(const float4*)&A[(size_t)r * lda + k0 + lk];
            if (FUSEA) {
                float4 v2 = *(const float4*)&A2[(size_t)(r ^ 2047) * lda + k0 + lk];
                v.x += v2.x; v.y += v2.y; v.z += v2.z; v.w += v2.w;
            }
            pa[i] = v;
        }
#pragma unroll
        for (int i = 0; i < WV; i++) {
            int r = colBase + lr + 64 * i;
            pw[i] = *(const float4*)&W[(size_t)r * K + k0 + lk];
        }
    };

    auto split_store = [&](float4 v, float* hrow, float* lrow) {
        float4 h, l;
        h.x = __uint_as_float(f2tf(v.x)); l.x = __uint_as_float(f2tf(v.x - h.x));
        h.y = __uint_as_float(f2tf(v.y)); l.y = __uint_as_float(f2tf(v.y - h.y));
        h.z = __uint_as_float(f2tf(v.z)); l.z = __uint_as_float(f2tf(v.z - h.z));
        h.w = __uint_as_float(f2tf(v.w)); l.w = __uint_as_float(f2tf(v.w - h.w));
        *(float4*)hrow = h;
        *(float4*)lrow = l;
    };

    auto store_s = [&]() {
#pragma unroll
        for (int i = 0; i < AV; i++) {
            int r = lr + 64 * i;
            split_store(pa[i], &Ah[r][lk], &Al[r][lk]);
        }
#pragma unroll
        for (int i = 0; i < WV; i++) {
            int r = lr + 64 * i;
            split_store(pw[i], &Wh[r][lk], &Wl[r][lk]);
        }
    };

    float4 acc[2][NT];
#pragma unroll
    for (int mt = 0; mt < 2; mt++)
#pragma unroll
        for (int nt = 0; nt < NT; nt++) acc[mt][nt] = make_float4(0.f, 0.f, 0.f, 0.f);

    load_g(0);
    int k0 = 0;
    for (;;) {
        __syncthreads();                 // previous compute done before overwrite
        store_s();
        __syncthreads();
        const bool has_next = (k0 + BK < K);
        if (has_next) load_g(k0 + BK);   // prefetch next tile into regs during compute

#pragma unroll
        for (int kk = 0; kk < BK; kk += 8) {
            uint32_t ah[2][4], al[2][4];
#pragma unroll
            for (int mt = 0; mt < 2; mt++) {
                int r0 = wrow * 32 + mt * 16 + qid;
                ah[mt][0] = __float_as_uint(Ah[r0    ][kk + tig    ]);
                ah[mt][1] = __float_as_uint(Ah[r0 + 8][kk + tig    ]);
                ah[mt][2] = __float_as_uint(Ah[r0    ][kk + tig + 4]);
                ah[mt][3] = __float_as_uint(Ah[r0 + 8][kk + tig + 4]);
                al[mt][0] = __float_as_uint(Al[r0    ][kk + tig    ]);
                al[mt][1] = __float_as_uint(Al[r0 + 8][kk + tig    ]);
                al[mt][2] = __float_as_uint(Al[r0    ][kk + tig + 4]);
                al[mt][3] = __float_as_uint(Al[r0 + 8][kk + tig + 4]);
            }
#pragma unroll
            for (int nt = 0; nt < NT; nt++) {
                int c0 = wcol * (BN / 2) + nt * 8 + qid;
                uint32_t bh[2], bl[2];
                bh[0] = __float_as_uint(Wh[c0][kk + tig    ]);
                bh[1] = __float_as_uint(Wh[c0][kk + tig + 4]);
                bl[0] = __float_as_uint(Wl[c0][kk + tig    ]);
                bl[1] = __float_as_uint(Wl[c0][kk + tig + 4]);
#pragma unroll
                for (int mt = 0; mt < 2; mt++) {
                    mma8(acc[mt][nt], ah[mt], bh);
                    mma8(acc[mt][nt], ah[mt], bl);
                    mma8(acc[mt][nt], al[mt], bh);
                }
            }
        }
        if (!has_next) break;
        k0 += BK;
    }

    // ---- epilogue ----
#pragma unroll
    for (int mt = 0; mt < 2; mt++) {
#pragma unroll
        for (int nt = 0; nt < NT; nt++) {
            int r0 = rowBase + wrow * 32 + mt * 16 + qid;
            int c  = colBase + wcol * (BN / 2) + nt * 8 + tig * 2;
            float4 v = acc[mt][nt];
            if (EPI == 1) {
                float b0 = bias[c], b1 = bias[c + 1];
                v.x = softplus_f(v.x + b0); v.y = softplus_f(v.y + b1);
                v.z = softplus_f(v.z + b0); v.w = softplus_f(v.w + b1);
            }
            *(float2*)&C[(size_t)r0 * N + c]       = make_float2(v.x, v.y);
            *(float2*)&C[(size_t)(r0 + 8) * N + c] = make_float2(v.z, v.w);
        }
    }
}

// ---------------- depthwise causal conv (K=4) + SiLU, both directions ----------------
__global__ void conv_silu_kernel(const float* __restrict__ cw_f, const float* __restrict__ cb_f,
                                 const float* __restrict__ cw_r, const float* __restrict__ cb_r)
{
    int idx = blockIdx.x * blockDim.x + threadIdx.x;
    if (idx >= 2 * NR * DI) return;
    int d   = idx % DI;
    int r   = (idx / DI) % NR;
    int dir = idx / (DI * NR);
    int b = r / LSEQ, t = r % LSEQ;

    const float* cw = dir ? cw_r : cw_f;
    const float* cb = dir ? cb_r : cb_f;

    float accv = cb[d];
#pragma unroll
    for (int k = 0; k < 4; k++) {
        int tt = t - 3 + k;
        if (tt >= 0) {
            int ts = dir ? (LSEQ - 1 - tt) : tt;
            accv += cw[d * 4 + k] * g_xz[(size_t)(b * LSEQ + ts) * (2 * DI) + d];
        }
    }
    float s = accv / (1.f + __expf(-accv));
    g_xc[dir][(size_t)r * DI + d] = s;
}

// ---------------- selective scan: warp = 2 channels x 16 states, pipelined ----------------
__global__ void __launch_bounds__(256)
scan_kernel(const float* __restrict__ Alog_f, const float* __restrict__ D_f,
            const float* __restrict__ Alog_r, const float* __restrict__ D_r)
{
    int w    = (blockIdx.x * blockDim.x + threadIdx.x) / 32;  // 0..4095
    int lane = threadIdx.x % 32;
    int c = lane / 16;      // channel within warp (0/1)
    int n = lane % 16;      // state index

    int dir = w / 2048;
    int rem = w % 2048;
    int b   = rem / 512;
    int d   = (rem % 512) * 2 + c;

    const float* Alog = dir ? Alog_r : Alog_f;
    const float* Dp   = dir ? D_r   : D_f;

    const float Av = -expf(Alog[d * DS + n]);
    const float Dd = Dp[d];

    const float* dtp = &g_dt[dir][(size_t)(b * LSEQ) * DI + d];
    const float* xp  = &g_xc[dir][(size_t)(b * LSEQ) * DI + d];
    const float* bp  = &g_xdbl[dir][(size_t)(b * LSEQ) * 64 + DTR + n];
    const float* cp  = bp + DS;
    float*       yp  = &g_y[dir][(size_t)(b * LSEQ) * DI + d];

    const float* zp = &g_xz[(size_t)(b * LSEQ + (dir ? LSEQ - 1 : 0)) * (2 * DI) + DI + d];
    const long  zstep = dir ? -(long)(2 * DI) : (long)(2 * DI);

    float h = 0.f;

    float dtv = dtp[0];
    float xv  = xp[0];
    float Bv  = bp[0];
    float Cv  = cp[0];

    auto step = [&](int t, float dt_c, float x_c, float B_c, float C_c) {
        float dA = __expf(dt_c * Av);
        h = dA * h + (dt_c * x_c) * B_c;

        float p = h * C_c;
        p += __shfl_xor_sync(0xffffffffu, p, 8);
        p += __shfl_xor_sync(0xffffffffu, p, 4);
        p += __shfl_xor_sync(0xffffffffu, p, 2);
        p += __shfl_xor_sync(0xffffffffu, p, 1);

        if (n == 0) {
            float zv = *zp;
            float y  = p + Dd * x_c;
            float zs = zv / (1.f + __expf(-zv));
            yp[(size_t)t * DI] = y * zs;
        }
        zp += zstep;
    };

#pragma unroll 2
    for (int t = 0; t < LSEQ - 1; t++) {
        float dtn = dtp[(size_t)(t + 1) * DI];
        float xn  = xp [(size_t)(t + 1) * DI];
        float Bn  = bp [(size_t)(t + 1) * 64];
        float Cn  = cp [(size_t)(t + 1) * 64];

        step(t, dtv, xv, Bv, Cv);

        dtv = dtn; xv = xn; Bv = Bn; Cv = Cn;
    }
    step(LSEQ - 1, dtv, xv, Bv, Cv);
}

// ---------------- launch ----------------
extern "C" void kernel_launch(void* const* d_in, const int* in_sizes, int n_in,
                              void* d_out, int out_size)
{
    const float* hidden = (const float*)d_in[0];
    const float* W_in   = (const float*)d_in[1];
    const float* W_out  = (const float*)d_in[2];
    const float* cw_f   = (const float*)d_in[3];
    const float* cb_f   = (const float*)d_in[4];
    const float* Wx_f   = (const float*)d_in[5];
    const float* Wdt_f  = (const float*)d_in[6];
    const float* bdt_f  = (const float*)d_in[7];
    const float* Alog_f = (const float*)d_in[8];
    const float* D_f    = (const float*)d_in[9];
    const float* cw_r   = (const float*)d_in[10];
    const float* cb_r   = (const float*)d_in[11];
    const float* Wx_r   = (const float*)d_in[12];
    const float* Wdt_r  = (const float*)d_in[13];
    const float* bdt_r  = (const float*)d_in[14];
    const float* Alog_r = (const float*)d_in[15];
    const float* D_r    = (const float*)d_in[16];
    float* out = (float*)d_out;

    float* xz;   cudaGetSymbolAddress((void**)&xz,   g_xz);
    float* xc;   cudaGetSymbolAddress((void**)&xc,   g_xc);
    float* xdbl; cudaGetSymbolAddress((void**)&xdbl, g_xdbl);
    float* dtb;  cudaGetSymbolAddress((void**)&dtb,  g_dt);
    float* yb;   cudaGetSymbolAddress((void**)&yb,   g_y);

    // 1) xz = hidden @ W_in^T   [8192,512] x [2048,512]^T -> [8192,2048]
    {
        dim3 grid((2 * DI) / 128, NR / 128, 1);
        gemm_tf32<128, 128, 0, 0><<<grid, 256>>>(hidden, nullptr, DM, W_in, nullptr, xz,
                                                 NR, 2 * DI, DM, nullptr, nullptr, 0, 0);
    }

    // 2) conv + silu (both dirs)
    {
        int total = 2 * NR * DI;
        conv_silu_kernel<<<(total + 255) / 256, 256>>>(cw_f, cb_f, cw_r, cb_r);
    }

    // 3) x_dbl = xc @ W_x^T  [8192,1024] x [64,1024]^T -> [8192,64]  (dirs batched on z)
    {
        dim3 grid(1, NR / 128, 2);
        gemm_tf32<128, 64, 0, 0><<<grid, 256>>>(xc, nullptr, DI, Wx_f, Wx_r, xdbl,
                                                NR, 64, DI, nullptr, nullptr,
                                                (long)NR * DI, (long)NR * 64);
    }

    // 4) dt = softplus(dt_r @ W_dt^T + b_dt)  [8192,32] x [1024,32]^T -> [8192,1024]
    {
        dim3 grid(DI / 128, NR / 128, 2);
        gemm_tf32<128, 128, 1, 0><<<grid, 256>>>(xdbl, nullptr, 64, Wdt_f, Wdt_r, dtb,
                                                 NR, DI, DTR, bdt_f, bdt_r,
                                                 (long)NR * 64, (long)NR * DI);
    }

    // 5) selective scan (both dirs): 4096 warps
    scan_kernel<<<512, 256>>>(Alog_f, D_f, Alog_r, D_r);

    // 6+7) out = (y_fwd + reverse(y_rev)) @ W_out^T  [8192,1024] x [512,1024]^T -> [8192,512]
    {
        dim3 grid(DM / 128, NR / 128, 1);
        gemm_tf32<128, 128, 0, 1><<<grid, 256>>>(yb, yb + (size_t)NR * DI, DI, W_out, nullptr, out,
                                                 NR, DM, DI, nullptr, nullptr, 0, 0);
    }
}

// round 6
// speedup vs baseline: 3.4943x; 1.8978x over previous
#include <cuda_runtime.h>
#include <math.h>
#include <stdint.h>

// Problem constants
#define BI   4
#define LSEQ 2048
#define DM   512
#define DI   1024      // d_inner
#define DS   16        // d_state
#define DTR  32        // dt_rank
#define NR   (BI*LSEQ) // 8192 rows (b*L flattened)

// ---------------- scratch (static device globals; no allocation) ----------------
__device__ float g_xz  [NR * 2 * DI];   // [row][2048]  x = [:1024], z = [1024:]
__device__ float g_xc  [2][NR * DI];    // conv+silu output per direction (dir-local time)
__device__ float g_xdbl[2][NR * 64];    // [row][64]: dt_r[0:32], B[32:48], C[48:64]
__device__ float g_dt  [2][NR * DI];    // softplus(dt) per direction
__device__ float g_y   [2][NR * DI];    // scan output per direction (dir-local time)

// ---------------- tf32 helpers ----------------
__device__ __forceinline__ uint32_t f2tf(float v) {
    uint32_t r; asm("cvt.rna.tf32.f32 %0, %1;" : "=r"(r) : "f"(v)); return r;
}

__device__ __forceinline__ void mma8(float4& d, const uint32_t* a, const uint32_t* b) {
    asm volatile("mma.sync.aligned.m16n8k8.row.col.f32.tf32.tf32.f32 "
                 "{%0,%1,%2,%3}, {%4,%5,%6,%7}, {%8,%9}, {%0,%1,%2,%3};"
                 : "+f"(d.x), "+f"(d.y), "+f"(d.z), "+f"(d.w)
                 : "r"(a[0]), "r"(a[1]), "r"(a[2]), "r"(a[3]), "r"(b[0]), "r"(b[1]));
}

__device__ __forceinline__ float softplus_f(float t) {
    return (t > 20.f) ? t : log1pf(expf(t));
}

// ==================================================================================
// Split-tf32 tensor-core GEMM:  C[M,N] = A[M,K] @ W[N,K]^T   (full fp32-grade accuracy)
// ==================================================================================
template <int BM, int BN, int EPI, int FUSEA>
__global__ void __launch_bounds__(256, 1)
gemm_tf32(const float* __restrict__ A, const float* __restrict__ A2, int lda,
          const float* __restrict__ W0, const float* __restrict__ W1,
          float* __restrict__ C, int M, int N, int K,
          const float* __restrict__ bias0, const float* __restrict__ bias1,
          long sA, long sC)
{
    constexpr int BK = 16;
    constexpr int SS = BK + 4;
    constexpr int AV = BM / 64;
    constexpr int WV = BN / 64;
    constexpr int NT = BN / 16;

    __shared__ float Ah[BM][SS], Al[BM][SS];
    __shared__ float Wh[BN][SS], Wl[BN][SS];

    const float* W    = blockIdx.z ? W1    : W0;
    const float* bias = blockIdx.z ? bias1 : bias0;
    A += (long)blockIdx.z * sA;
    C += (long)blockIdx.z * sC;

    const int tid  = threadIdx.x;
    const int warp = tid >> 5, lane = tid & 31;
    const int wrow = warp & 3, wcol = warp >> 2;
    const int rowBase = blockIdx.y * BM;
    const int colBase = blockIdx.x * BN;
    const int lr = tid >> 2;
    const int lk = (tid & 3) * 4;
    const int qid = lane >> 2, tig = lane & 3;

    float4 pa[AV], pw[WV];

    auto load_g = [&](int k0) {
#pragma unroll
        for (int i = 0; i < AV; i++) {
            int r = rowBase + lr + 64 * i;
            float4 v = *(const float4*)&A[(size_t)r * lda + k0 + lk];
            if (FUSEA) {
                float4 v2 = *(const float4*)&A2[(size_t)(r ^ 2047) * lda + k0 + lk];
                v.x += v2.x; v.y += v2.y; v.z += v2.z; v.w += v2.w;
            }
            pa[i] = v;
        }
#pragma unroll
        for (int i = 0; i < WV; i++) {
            int r = colBase + lr + 64 * i;
            pw[i] = *(const float4*)&W[(size_t)r * K + k0 + lk];
        }
    };

    auto split_store = [&](float4 v, float* hrow, float* lrow) {
        float4 h, l;
        h.x = __uint_as_float(f2tf(v.x)); l.x = __uint_as_float(f2tf(v.x - h.x));
        h.y = __uint_as_float(f2tf(v.y)); l.y = __uint_as_float(f2tf(v.y - h.y));
        h.z = __uint_as_float(f2tf(v.z)); l.z = __uint_as_float(f2tf(v.z - h.z));
        h.w = __uint_as_float(f2tf(v.w)); l.w = __uint_as_float(f2tf(v.w - h.w));
        *(float4*)hrow = h;
        *(float4*)lrow = l;
    };

    auto store_s = [&]() {
#pragma unroll
        for (int i = 0; i < AV; i++) {
            int r = lr + 64 * i;
            split_store(pa[i], &Ah[r][lk], &Al[r][lk]);
        }
#pragma unroll
        for (int i = 0; i < WV; i++) {
            int r = lr + 64 * i;
            split_store(pw[i], &Wh[r][lk], &Wl[r][lk]);
        }
    };

    float4 acc[2][NT];
#pragma unroll
    for (int mt = 0; mt < 2; mt++)
#pragma unroll
        for (int nt = 0; nt < NT; nt++) acc[mt][nt] = make_float4(0.f, 0.f, 0.f, 0.f);

    load_g(0);
    int k0 = 0;
    for (;;) {
        __syncthreads();
        store_s();
        __syncthreads();
        const bool has_next = (k0 + BK < K);
        if (has_next) load_g(k0 + BK);

#pragma unroll
        for (int kk = 0; kk < BK; kk += 8) {
            uint32_t ah[2][4], al[2][4];
#pragma unroll
            for (int mt = 0; mt < 2; mt++) {
                int r0 = wrow * 32 + mt * 16 + qid;
                ah[mt][0] = __float_as_uint(Ah[r0    ][kk + tig    ]);
                ah[mt][1] = __float_as_uint(Ah[r0 + 8][kk + tig    ]);
                ah[mt][2] = __float_as_uint(Ah[r0    ][kk + tig + 4]);
                ah[mt][3] = __float_as_uint(Ah[r0 + 8][kk + tig + 4]);
                al[mt][0] = __float_as_uint(Al[r0    ][kk + tig    ]);
                al[mt][1] = __float_as_uint(Al[r0 + 8][kk + tig    ]);
                al[mt][2] = __float_as_uint(Al[r0    ][kk + tig + 4]);
                al[mt][3] = __float_as_uint(Al[r0 + 8][kk + tig + 4]);
            }
#pragma unroll
            for (int nt = 0; nt < NT; nt++) {
                int c0 = wcol * (BN / 2) + nt * 8 + qid;
                uint32_t bh[2], bl[2];
                bh[0] = __float_as_uint(Wh[c0][kk + tig    ]);
                bh[1] = __float_as_uint(Wh[c0][kk + tig + 4]);
                bl[0] = __float_as_uint(Wl[c0][kk + tig    ]);
                bl[1] = __float_as_uint(Wl[c0][kk + tig + 4]);
#pragma unroll
                for (int mt = 0; mt < 2; mt++) {
                    mma8(acc[mt][nt], ah[mt], bh);
                    mma8(acc[mt][nt], ah[mt], bl);
                    mma8(acc[mt][nt], al[mt], bh);
                }
            }
        }
        if (!has_next) break;
        k0 += BK;
    }

#pragma unroll
    for (int mt = 0; mt < 2; mt++) {
#pragma unroll
        for (int nt = 0; nt < NT; nt++) {
            int r0 = rowBase + wrow * 32 + mt * 16 + qid;
            int c  = colBase + wcol * (BN / 2) + nt * 8 + tig * 2;
            float4 v = acc[mt][nt];
            if (EPI == 1) {
                float b0 = bias[c], b1 = bias[c + 1];
                v.x = softplus_f(v.x + b0); v.y = softplus_f(v.y + b1);
                v.z = softplus_f(v.z + b0); v.w = softplus_f(v.w + b1);
            }
            *(float2*)&C[(size_t)r0 * N + c]       = make_float2(v.x, v.y);
            *(float2*)&C[(size_t)(r0 + 8) * N + c] = make_float2(v.z, v.w);
        }
    }
}

// ---------------- depthwise causal conv (K=4) + SiLU, both directions ----------------
__global__ void conv_silu_kernel(const float* __restrict__ cw_f, const float* __restrict__ cb_f,
                                 const float* __restrict__ cw_r, const float* __restrict__ cb_r)
{
    int idx = blockIdx.x * blockDim.x + threadIdx.x;
    if (idx >= 2 * NR * DI) return;
    int d   = idx % DI;
    int r   = (idx / DI) % NR;
    int dir = idx / (DI * NR);
    int b = r / LSEQ, t = r % LSEQ;

    const float* cw = dir ? cw_r : cw_f;
    const float* cb = dir ? cb_r : cb_f;

    float accv = cb[d];
#pragma unroll
    for (int k = 0; k < 4; k++) {
        int tt = t - 3 + k;
        if (tt >= 0) {
            int ts = dir ? (LSEQ - 1 - tt) : tt;
            accv += cw[d * 4 + k] * g_xz[(size_t)(b * LSEQ + ts) * (2 * DI) + d];
        }
    }
    float s = accv / (1.f + __expf(-accv));
    g_xc[dir][(size_t)r * DI + d] = s;
}

// ==================================================================================
// Selective scan v2: block-cooperative smem staging + cp.async double buffering.
// Block = 8 warps, shares (dir, b) and 16 consecutive channels d0..d0+15.
// Warp w handles channels d0+2w (lanes 0-15) and d0+2w+1 (lanes 16-31); lane%16 = state.
// Chunks of SCAN_T=32 timesteps staged into smem with coalesced cp.async loads.
// ==================================================================================
#define SCAN_T 32
#define NCHUNK (LSEQ / SCAN_T)

__device__ __forceinline__ void cpa4(uint32_t s, const void* g) {
    asm volatile("cp.async.ca.shared.global [%0], [%1], 4;" :: "r"(s), "l"(g));
}
__device__ __forceinline__ void cpa_commit() {
    asm volatile("cp.async.commit_group;" ::: "memory");
}
__device__ __forceinline__ void cpa_wait1() {
    asm volatile("cp.async.wait_group 1;" ::: "memory");
}

__global__ void __launch_bounds__(256, 1)
scan_kernel(const float* __restrict__ Alog_f, const float* __restrict__ D_f,
            const float* __restrict__ Alog_r, const float* __restrict__ D_r)
{
    __shared__ float s_dt[2][SCAN_T][16];
    __shared__ float s_x [2][SCAN_T][16];
    __shared__ float s_z [2][SCAN_T][16];
    __shared__ float s_B [2][SCAN_T][16];
    __shared__ float s_C [2][SCAN_T][16];

    const int bx  = blockIdx.x;        // 0..511
    const int dir = bx >> 8;
    const int rem = bx & 255;
    const int b   = rem >> 6;          // 0..3
    const int d0  = (rem & 63) << 4;   // channel group base

    const int tid  = threadIdx.x;
    const int w    = tid >> 5;
    const int lane = tid & 31;
    const int c    = lane >> 4;        // sub-channel within warp
    const int n    = lane & 15;        // state index
    const int dd   = 2 * w + c;        // local channel 0..15
    const int d    = d0 + dd;

    const float* Alog = dir ? Alog_r : Alog_f;
    const float* Dp   = dir ? D_r   : D_f;
    const float Av = -expf(Alog[d * DS + n]);
    const float Dd = Dp[d];

    const float* dt_base = &g_dt[dir][(size_t)(b * LSEQ) * DI + d0];
    const float* x_base  = &g_xc[dir][(size_t)(b * LSEQ) * DI + d0];
    const float* bc_base = &g_xdbl[dir][(size_t)(b * LSEQ) * 64 + DTR];
    const float* z_base  = &g_xz[(size_t)(b * LSEQ) * (2 * DI) + DI + d0];

    // cooperative chunk load: 512 elements per array, 2 per thread
    auto load_chunk = [&](int buf, int t0) {
#pragma unroll
        for (int j = 0; j < 2; j++) {
            int e  = j * 256 + tid;
            int tt = e >> 4;
            int k  = e & 15;
            int t  = t0 + tt;
            size_t row = (size_t)t;
            cpa4((uint32_t)__cvta_generic_to_shared(&s_dt[buf][tt][k]), dt_base + row * DI + k);
            cpa4((uint32_t)__cvta_generic_to_shared(&s_x [buf][tt][k]), x_base  + row * DI + k);
            int torig = dir ? (LSEQ - 1 - t) : t;
            cpa4((uint32_t)__cvta_generic_to_shared(&s_z [buf][tt][k]), z_base + (size_t)torig * (2 * DI) + k);
            cpa4((uint32_t)__cvta_generic_to_shared(&s_B [buf][tt][k]), bc_base + row * 64 + k);
            cpa4((uint32_t)__cvta_generic_to_shared(&s_C [buf][tt][k]), bc_base + row * 64 + DS + k);
        }
        cpa_commit();
    };

    load_chunk(0, 0);
    load_chunk(1, SCAN_T);
    cpa_wait1();          // chunk 0 resident
    __syncthreads();

    float h = 0.f;
    float* yp = &g_y[dir][(size_t)(b * LSEQ) * DI + d];

    for (int ch = 0; ch < NCHUNK; ch++) {
        const int buf = ch & 1;
#pragma unroll 8
        for (int tt = 0; tt < SCAN_T; tt++) {
            float dtv = s_dt[buf][tt][dd];
            float xv  = s_x [buf][tt][dd];
            float Bv  = s_B [buf][tt][n];
            float Cv  = s_C [buf][tt][n];

            float dA = __expf(dtv * Av);
            h = dA * h + (dtv * xv) * Bv;

            float p = h * Cv;
            p += __shfl_xor_sync(0xffffffffu, p, 8);
            p += __shfl_xor_sync(0xffffffffu, p, 4);
            p += __shfl_xor_sync(0xffffffffu, p, 2);
            p += __shfl_xor_sync(0xffffffffu, p, 1);

            if (n == 0) {
                float zv = s_z[buf][tt][dd];
                float zs = zv / (1.f + __expf(-zv));
                *yp = (p + Dd * xv) * zs;
            }
            yp += DI;
        }
        __syncthreads();                      // all warps done with buf
        if (ch + 2 < NCHUNK) load_chunk(buf, (ch + 2) * SCAN_T);
        else                 cpa_commit();    // empty group keeps wait count aligned
        cpa_wait1();                          // next chunk resident
        __syncthreads();
    }
}

// ---------------- launch ----------------
extern "C" void kernel_launch(void* const* d_in, const int* in_sizes, int n_in,
                              void* d_out, int out_size)
{
    const float* hidden = (const float*)d_in[0];
    const float* W_in   = (const float*)d_in[1];
    const float* W_out  = (const float*)d_in[2];
    const float* cw_f   = (const float*)d_in[3];
    const float* cb_f   = (const float*)d_in[4];
    const float* Wx_f   = (const float*)d_in[5];
    const float* Wdt_f  = (const float*)d_in[6];
    const float* bdt_f  = (const float*)d_in[7];
    const float* Alog_f = (const float*)d_in[8];
    const float* D_f    = (const float*)d_in[9];
    const float* cw_r   = (const float*)d_in[10];
    const float* cb_r   = (const float*)d_in[11];
    const float* Wx_r   = (const float*)d_in[12];
    const float* Wdt_r  = (const float*)d_in[13];
    const float* bdt_r  = (const float*)d_in[14];
    const float* Alog_r = (const float*)d_in[15];
    const float* D_r    = (const float*)d_in[16];
    float* out = (float*)d_out;

    float* xz;   cudaGetSymbolAddress((void**)&xz,   g_xz);
    float* xc;   cudaGetSymbolAddress((void**)&xc,   g_xc);
    float* xdbl; cudaGetSymbolAddress((void**)&xdbl, g_xdbl);
    float* dtb;  cudaGetSymbolAddress((void**)&dtb,  g_dt);
    float* yb;   cudaGetSymbolAddress((void**)&yb,   g_y);

    // 1) xz = hidden @ W_in^T   [8192,512] x [2048,512]^T -> [8192,2048]
    {
        dim3 grid((2 * DI) / 128, NR / 128, 1);
        gemm_tf32<128, 128, 0, 0><<<grid, 256>>>(hidden, nullptr, DM, W_in, nullptr, xz,
                                                 NR, 2 * DI, DM, nullptr, nullptr, 0, 0);
    }

    // 2) conv + silu (both dirs)
    {
        int total = 2 * NR * DI;
        conv_silu_kernel<<<(total + 255) / 256, 256>>>(cw_f, cb_f, cw_r, cb_r);
    }

    // 3) x_dbl = xc @ W_x^T  [8192,1024] x [64,1024]^T -> [8192,64]  (dirs batched on z)
    {
        dim3 grid(1, NR / 128, 2);
        gemm_tf32<128, 64, 0, 0><<<grid, 256>>>(xc, nullptr, DI, Wx_f, Wx_r, xdbl,
                                                NR, 64, DI, nullptr, nullptr,
                                                (long)NR * DI, (long)NR * 64);
    }

    // 4) dt = softplus(dt_r @ W_dt^T + b_dt)  [8192,32] x [1024,32]^T -> [8192,1024]
    {
        dim3 grid(DI / 128, NR / 128, 2);
        gemm_tf32<128, 128, 1, 0><<<grid, 256>>>(xdbl, nullptr, 64, Wdt_f, Wdt_r, dtb,
                                                 NR, DI, DTR, bdt_f, bdt_r,
                                                 (long)NR * 64, (long)NR * DI);
    }

    // 5) selective scan (both dirs): 512 blocks x 8 warps, smem-staged chunks
    scan_kernel<<<512, 256>>>(Alog_f, D_f, Alog_r, D_r);

    // 6+7) out = (y_fwd + reverse(y_rev)) @ W_out^T  [8192,1024] x [512,1024]^T -> [8192,512]
    {
        dim3 grid(DM / 128, NR / 128, 1);
        gemm_tf32<128, 128, 0, 1><<<grid, 256>>>(yb, yb + (size_t)NR * DI, DI, W_out, nullptr, out,
                                                 NR, DM, DI, nullptr, nullptr, 0, 0);
    }
}

// round 9
// speedup vs baseline: 3.5463x; 1.0149x over previous
#include <cuda_runtime.h>
#include <math.h>
#include <stdint.h>

// Problem constants
#define BI   4
#define LSEQ 2048
#define DM   512
#define DI   1024      // d_inner
#define DS   16        // d_state
#define DTR  32        // dt_rank
#define NR   (BI*LSEQ) // 8192 rows (b*L flattened)

// ---------------- scratch (static device globals; no allocation) ----------------
__device__ float g_xz  [NR * 2 * DI];   // [row][2048]  x = [:1024], z = [1024:]
__device__ float g_xc  [2][NR * DI];    // conv+silu output per direction (dir-local time)
__device__ float g_xdbl[2][NR * 64];    // [row][64]: dt_r[0:32], B[32:48], C[48:64]
__device__ float g_dt  [2][NR * DI];    // softplus(dt) per direction
__device__ float g_y   [2][NR * DI];    // scan output per direction (dir-local time)

// ---------------- tf32 helpers ----------------
__device__ __forceinline__ float f2tf(float v) {
    uint32_t r; asm("cvt.rna.tf32.f32 %0, %1;" : "=r"(r) : "f"(v));
    return __uint_as_float(r);
}

__device__ __forceinline__ void mma8(float4& d, const uint32_t* a, const uint32_t* b) {
    asm volatile("mma.sync.aligned.m16n8k8.row.col.f32.tf32.tf32.f32 "
                 "{%0,%1,%2,%3}, {%4,%5,%6,%7}, {%8,%9}, {%0,%1,%2,%3};"
                 : "+f"(d.x), "+f"(d.y), "+f"(d.z), "+f"(d.w)
                 : "r"(a[0]), "r"(a[1]), "r"(a[2]), "r"(a[3]), "r"(b[0]), "r"(b[1]));
}

__device__ __forceinline__ float softplus_f(float t) {
    return (t > 20.f) ? t : log1pf(expf(t));
}

// ==================================================================================
// Split-tf32 tensor-core GEMM:  C[M,N] = A[M,K] @ W[N,K]^T  (fp32-grade accuracy)
// Fragment-order shared memory: staging writes tf32 hi/lo values directly into
// per-lane MMA fragment positions, so the mainloop does vectorized LDS.128/LDS.64.
// BM=128 fixed; BK=16 (two k8 MMA steps per tile); 256 threads; 2 CTAs/SM.
//
// A fragment layout  Af[s][g][qid][tig'][slot], slot = (row&8?1:0) + (khalf?2:0)
//   tig' = tig ^ (qid&3) ^ (2*s)                       (swizzle; LDS conflict-free)
// B fragment layout  Bf[s][n][tig'][kh], tig' = tig ^ (((n&1)<<1) ^ s)
// ==================================================================================
template <int BN, int EPI, int FUSEA>
__global__ void __launch_bounds__(256, 2)
gemm_tf32(const float* __restrict__ A, const float* __restrict__ A2, int lda,
          const float* __restrict__ W0, const float* __restrict__ W1,
          float* __restrict__ C, int M, int N, int K,
          const float* __restrict__ bias0, const float* __restrict__ bias1,
          long sA_stride, long sC_stride)
{
    constexpr int BM = 128, BK = 16;
    constexpr int G  = BM / 16;      // 8 row-groups
    constexpr int NT = BN / 16;      // 8-col tiles per warp
    constexpr int AV = BM / 64;      // 2
    constexpr int WV = BN / 64;      // 1 or 2

    __shared__ float Afh[2][G][8][4][4];
    __shared__ float Afl[2][G][8][4][4];
    __shared__ float Bfh[2][BN][4][2];
    __shared__ float Bfl[2][BN][4][2];

    const float* W    = blockIdx.z ? W1    : W0;
    const float* bias = blockIdx.z ? bias1 : bias0;
    A += (long)blockIdx.z * sA_stride;
    C += (long)blockIdx.z * sC_stride;

    const int tid  = threadIdx.x;
    const int warp = tid >> 5, lane = tid & 31;
    const int wrow = warp & 3, wcol = warp >> 2;
    const int rowBase = blockIdx.y * BM;
    const int colBase = blockIdx.x * BN;
    const int lr = tid >> 2;           // 0..63
    const int lk = (tid & 3) * 4;      // 0,4,8,12
    const int qid = lane >> 2, tig = lane & 3;

    // staging constants (thread's k range lk..lk+3 is within one k8 step & one k-half)
    const int sA  = lk >> 3;           // which k8 step
    const int khA = (lk >> 2) & 1;     // k half within step

    float4 pa[AV], pw[WV];

    auto load_g = [&](int k0) {
#pragma unroll
        for (int i = 0; i < AV; i++) {
            int r = rowBase + lr + 64 * i;
            float4 v = *(const float4*)&A[(size_t)r * lda + k0 + lk];
            if (FUSEA) {
                float4 v2 = *(const float4*)&A2[(size_t)(r ^ 2047) * lda + k0 + lk];
                v.x += v2.x; v.y += v2.y; v.z += v2.z; v.w += v2.w;
            }
            pa[i] = v;
        }
#pragma unroll
        for (int i = 0; i < WV; i++) {
            int r = colBase + lr + 64 * i;
            pw[i] = *(const float4*)&W[(size_t)r * K + k0 + lk];
        }
    };

    auto store_s = [&]() {
#pragma unroll
        for (int i = 0; i < AV; i++) {
            int r   = lr + 64 * i;
            int g   = r >> 4;
            int q   = r & 7;
            int slot = ((r >> 3) & 1) + 2 * khA;
            const float* v = &pa[i].x;
#pragma unroll
            for (int j = 0; j < 4; j++) {
                int jj = j ^ (q & 3) ^ (2 * sA);
                float h = f2tf(v[j]);
                Afh[sA][g][q][jj][slot] = h;
                Afl[sA][g][q][jj][slot] = f2tf(v[j] - h);
            }
        }
#pragma unroll
        for (int i = 0; i < WV; i++) {
            int n = lr + 64 * i;
            int cb = ((n & 1) << 1) ^ sA;
            const float* v = &pw[i].x;
#pragma unroll
            for (int j = 0; j < 4; j++) {
                int jj = j ^ cb;
                float h = f2tf(v[j]);
                Bfh[sA][n][jj][khA] = h;
                Bfl[sA][n][jj][khA] = f2tf(v[j] - h);
            }
        }
    };

    float4 acc[2][NT];
#pragma unroll
    for (int mt = 0; mt < 2; mt++)
#pragma unroll
        for (int nt = 0; nt < NT; nt++) acc[mt][nt] = make_float4(0.f, 0.f, 0.f, 0.f);

    load_g(0);
    int k0 = 0;
    for (;;) {
        __syncthreads();               // previous tile's reads done
        store_s();
        __syncthreads();               // fragments visible
        const bool has_next = (k0 + BK < K);
        if (has_next) load_g(k0 + BK); // overlap global latency with MMAs

#pragma unroll
        for (int s = 0; s < 2; s++) {
            const int ptA = tig ^ (qid & 3) ^ (2 * s);
            uint32_t ah[2][4], al[2][4];
#pragma unroll
            for (int mt = 0; mt < 2; mt++) {
                int g = wrow * 2 + mt;
                *(uint4*)ah[mt] = *(const uint4*)&Afh[s][g][qid][ptA][0];
                *(uint4*)al[mt] = *(const uint4*)&Afl[s][g][qid][ptA][0];
            }
            const int ptB = tig ^ (((qid & 1) << 1) ^ s);
#pragma unroll
            for (int nt = 0; nt < NT; nt++) {
                int n = wcol * (BN / 2) + nt * 8 + qid;
                uint32_t bh[2], bl[2];
                *(uint2*)bh = *(const uint2*)&Bfh[s][n][ptB][0];
                *(uint2*)bl = *(const uint2*)&Bfl[s][n][ptB][0];
#pragma unroll
                for (int mt = 0; mt < 2; mt++) {
                    mma8(acc[mt][nt], ah[mt], bh);
                    mma8(acc[mt][nt], ah[mt], bl);
                    mma8(acc[mt][nt], al[mt], bh);
                }
            }
        }
        if (!has_next) break;
        k0 += BK;
    }

    // ---- epilogue ----
#pragma unroll
    for (int mt = 0; mt < 2; mt++) {
#pragma unroll
        for (int nt = 0; nt < NT; nt++) {
            int r0 = rowBase + wrow * 32 + mt * 16 + qid;
            int c  = colBase + wcol * (BN / 2) + nt * 8 + tig * 2;
            float4 v = acc[mt][nt];
            if (EPI == 1) {
                float b0 = bias[c], b1 = bias[c + 1];
                v.x = softplus_f(v.x + b0); v.y = softplus_f(v.y + b1);
                v.z = softplus_f(v.z + b0); v.w = softplus_f(v.w + b1);
            }
            *(float2*)&C[(size_t)r0 * N + c]       = make_float2(v.x, v.y);
            *(float2*)&C[(size_t)(r0 + 8) * N + c] = make_float2(v.z, v.w);
        }
    }
}

// ---------------- depthwise causal conv (K=4) + SiLU, both directions ----------------
__global__ void conv_silu_kernel(const float* __restrict__ cw_f, const float* __restrict__ cb_f,
                                 const float* __restrict__ cw_r, const float* __restrict__ cb_r)
{
    int idx = blockIdx.x * blockDim.x + threadIdx.x;
    if (idx >= 2 * NR * DI) return;
    int d   = idx % DI;
    int r   = (idx / DI) % NR;
    int dir = idx / (DI * NR);
    int b = r / LSEQ, t = r % LSEQ;

    const float* cw = dir ? cw_r : cw_f;
    const float* cb = dir ? cb_r : cb_f;

    float accv = cb[d];
#pragma unroll
    for (int k = 0; k < 4; k++) {
        int tt = t - 3 + k;
        if (tt >= 0) {
            int ts = dir ? (LSEQ - 1 - tt) : tt;
            accv += cw[d * 4 + k] * g_xz[(size_t)(b * LSEQ + ts) * (2 * DI) + d];
        }
    }
    float s = accv / (1.f + __expf(-accv));
    g_xc[dir][(size_t)r * DI + d] = s;
}

// ==================================================================================
// Selective scan: block-cooperative smem staging + cp.async double buffering.
// ==================================================================================
#define SCAN_T 32
#define NCHUNK (LSEQ / SCAN_T)

__device__ __forceinline__ void cpa4(uint32_t s, const void* g) {
    asm volatile("cp.async.ca.shared.global [%0], [%1], 4;" :: "r"(s), "l"(g));
}
__device__ __forceinline__ void cpa_commit() {
    asm volatile("cp.async.commit_group;" ::: "memory");
}
__device__ __forceinline__ void cpa_wait1() {
    asm volatile("cp.async.wait_group 1;" ::: "memory");
}

__global__ void __launch_bounds__(256, 1)
scan_kernel(const float* __restrict__ Alog_f, const float* __restrict__ D_f,
            const float* __restrict__ Alog_r, const float* __restrict__ D_r)
{
    __shared__ float s_dt[2][SCAN_T][16];
    __shared__ float s_x [2][SCAN_T][16];
    __shared__ float s_z [2][SCAN_T][16];
    __shared__ float s_B [2][SCAN_T][16];
    __shared__ float s_C [2][SCAN_T][16];

    const int bx  = blockIdx.x;        // 0..511
    const int dir = bx >> 8;
    const int rem = bx & 255;
    const int b   = rem >> 6;          // 0..3
    const int d0  = (rem & 63) << 4;   // channel group base

    const int tid  = threadIdx.x;
    const int w    = tid >> 5;
    const int lane = tid & 31;
    const int c    = lane >> 4;
    const int n    = lane & 15;
    const int dd   = 2 * w + c;
    const int d    = d0 + dd;

    const float* Alog = dir ? Alog_r : Alog_f;
    const float* Dp   = dir ? D_r   : D_f;
    const float Av = -expf(Alog[d * DS + n]);
    const float Dd = Dp[d];

    const float* dt_base = &g_dt[dir][(size_t)(b * LSEQ) * DI + d0];
    const float* x_base  = &g_xc[dir][(size_t)(b * LSEQ) * DI + d0];
    const float* bc_base = &g_xdbl[dir][(size_t)(b * LSEQ) * 64 + DTR];
    const float* z_base  = &g_xz[(size_t)(b * LSEQ) * (2 * DI) + DI + d0];

    auto load_chunk = [&](int buf, int t0) {
#pragma unroll
        for (int j = 0; j < 2; j++) {
            int e  = j * 256 + tid;
            int tt = e >> 4;
            int k  = e & 15;
            int t  = t0 + tt;
            size_t row = (size_t)t;
            cpa4((uint32_t)__cvta_generic_to_shared(&s_dt[buf][tt][k]), dt_base + row * DI + k);
            cpa4((uint32_t)__cvta_generic_to_shared(&s_x [buf][tt][k]), x_base  + row * DI + k);
            int torig = dir ? (LSEQ - 1 - t) : t;
            cpa4((uint32_t)__cvta_generic_to_shared(&s_z [buf][tt][k]), z_base + (size_t)torig * (2 * DI) + k);
            cpa4((uint32_t)__cvta_generic_to_shared(&s_B [buf][tt][k]), bc_base + row * 64 + k);
            cpa4((uint32_t)__cvta_generic_to_shared(&s_C [buf][tt][k]), bc_base + row * 64 + DS + k);
        }
        cpa_commit();
    };

    load_chunk(0, 0);
    load_chunk(1, SCAN_T);
    cpa_wait1();
    __syncthreads();

    float h = 0.f;
    float* yp = &g_y[dir][(size_t)(b * LSEQ) * DI + d];

    for (int ch = 0; ch < NCHUNK; ch++) {
        const int buf = ch & 1;
#pragma unroll 8
        for (int tt = 0; tt < SCAN_T; tt++) {
            float dtv = s_dt[buf][tt][dd];
            float xv  = s_x [buf][tt][dd];
            float Bv  = s_B [buf][tt][n];
            float Cv  = s_C [buf][tt][n];

            float dA = __expf(dtv * Av);
            h = dA * h + (dtv * xv) * Bv;

            float p = h * Cv;
            p += __shfl_xor_sync(0xffffffffu, p, 8);
            p += __shfl_xor_sync(0xffffffffu, p, 4);
            p += __shfl_xor_sync(0xffffffffu, p, 2);
            p += __shfl_xor_sync(0xffffffffu, p, 1);

            if (n == 0) {
                float zv = s_z[buf][tt][dd];
                float zs = zv / (1.f + __expf(-zv));
                *yp = (p + Dd * xv) * zs;
            }
            yp += DI;
        }
        __syncthreads();
        if (ch + 2 < NCHUNK) load_chunk(buf, (ch + 2) * SCAN_T);
        else                 cpa_commit();
        cpa_wait1();
        __syncthreads();
    }
}

// ---------------- launch ----------------
extern "C" void kernel_launch(void* const* d_in, const int* in_sizes, int n_in,
                              void* d_out, int out_size)
{
    const float* hidden = (const float*)d_in[0];
    const float* W_in   = (const float*)d_in[1];
    const float* W_out  = (const float*)d_in[2];
    const float* cw_f   = (const float*)d_in[3];
    const float* cb_f   = (const float*)d_in[4];
    const float* Wx_f   = (const float*)d_in[5];
    const float* Wdt_f  = (const float*)d_in[6];
    const float* bdt_f  = (const float*)d_in[7];
    const float* Alog_f = (const float*)d_in[8];
    const float* D_f    = (const float*)d_in[9];
    const float* cw_r   = (const float*)d_in[10];
    const float* cb_r   = (const float*)d_in[11];
    const float* Wx_r   = (const float*)d_in[12];
    const float* Wdt_r  = (const float*)d_in[13];
    const float* bdt_r  = (const float*)d_in[14];
    const float* Alog_r = (const float*)d_in[15];
    const float* D_r    = (const float*)d_in[16];
    float* out = (float*)d_out;

    float* xz;   cudaGetSymbolAddress((void**)&xz,   g_xz);
    float* xc;   cudaGetSymbolAddress((void**)&xc,   g_xc);
    float* xdbl; cudaGetSymbolAddress((void**)&xdbl, g_xdbl);
    float* dtb;  cudaGetSymbolAddress((void**)&dtb,  g_dt);
    float* yb;   cudaGetSymbolAddress((void**)&yb,   g_y);

    // 1) xz = hidden @ W_in^T   [8192,512] x [2048,512]^T -> [8192,2048]
    {
        dim3 grid((2 * DI) / 128, NR / 128, 1);
        gemm_tf32<128, 0, 0><<<grid, 256>>>(hidden, nullptr, DM, W_in, nullptr, xz,
                                            NR, 2 * DI, DM, nullptr, nullptr, 0, 0);
    }

    // 2) conv + silu (both dirs)
    {
        int total = 2 * NR * DI;
        conv_silu_kernel<<<(total + 255) / 256, 256>>>(cw_f, cb_f, cw_r, cb_r);
    }

    // 3) x_dbl = xc @ W_x^T  [8192,1024] x [64,1024]^T -> [8192,64]  (dirs batched on z)
    {
        dim3 grid(1, NR / 128, 2);
        gemm_tf32<64, 0, 0><<<grid, 256>>>(xc, nullptr, DI, Wx_f, Wx_r, xdbl,
                                           NR, 64, DI, nullptr, nullptr,
                                           (long)NR * DI, (long)NR * 64);
    }

    // 4) dt = softplus(dt_r @ W_dt^T + b_dt)  [8192,32] x [1024,32]^T -> [8192,1024]
    {
        dim3 grid(DI / 128, NR / 128, 2);
        gemm_tf32<128, 1, 0><<<grid, 256>>>(xdbl, nullptr, 64, Wdt_f, Wdt_r, dtb,
                                            NR, DI, DTR, bdt_f, bdt_r,
                                            (long)NR * 64, (long)NR * DI);
    }

    // 5) selective scan (both dirs): 512 blocks x 8 warps, smem-staged chunks
    scan_kernel<<<512, 256>>>(Alog_f, D_f, Alog_r, D_r);

    // 6+7) out = (y_fwd + reverse(y_rev)) @ W_out^T  [8192,1024] x [512,1024]^T -> [8192,512]
    {
        dim3 grid(DM / 128, NR / 128, 1);
        gemm_tf32<128, 0, 1><<<grid, 256>>>(yb, yb + (size_t)NR * DI, DI, W_out, nullptr, out,
                                            NR, DM, DI, nullptr, nullptr, 0, 0);
    }
}

// round 10
// speedup vs baseline: 4.5703x; 1.2887x over previous
#include <cuda_runtime.h>
#include <math.h>
#include <stdint.h>

// Problem constants
#define BI   4
#define LSEQ 2048
#define DM   512
#define DI   1024      // d_inner
#define DS   16        // d_state
#define DTR  32        // dt_rank
#define NR   (BI*LSEQ) // 8192 rows (b*L flattened)

// ---------------- scratch (static device globals; no allocation) ----------------
__device__ float g_xz  [NR * 2 * DI];   // [row][2048]  x = [:1024], z = [1024:]
__device__ float g_xc  [2][NR * DI];    // conv+silu output per direction (dir-local time)
__device__ float g_xdbl[2][NR * 64];    // [row][64]: dt_r[0:32], B[32:48], C[48:64]
__device__ float g_dt  [2][NR * DI];    // softplus(dt) per direction
__device__ float g_y   [2][NR * DI];    // scan output per direction (dir-local time)

// ---------------- tf32 helpers ----------------
__device__ __forceinline__ float f2tf(float v) {
    uint32_t r; asm("cvt.rna.tf32.f32 %0, %1;" : "=r"(r) : "f"(v));
    return __uint_as_float(r);
}

__device__ __forceinline__ void mma8(float4& d, const uint32_t* a, const uint32_t* b) {
    asm volatile("mma.sync.aligned.m16n8k8.row.col.f32.tf32.tf32.f32 "
                 "{%0,%1,%2,%3}, {%4,%5,%6,%7}, {%8,%9}, {%0,%1,%2,%3};"
                 : "+f"(d.x), "+f"(d.y), "+f"(d.z), "+f"(d.w)
                 : "r"(a[0]), "r"(a[1]), "r"(a[2]), "r"(a[3]), "r"(b[0]), "r"(b[1]));
}

__device__ __forceinline__ float softplus_f(float t) {
    return (t > 20.f) ? t : log1pf(expf(t));
}

// ==================================================================================
// Single-pass tf32 tensor-core GEMM:  C[M,N] = A[M,K] @ W[N,K]^T
// Fragment-order shared memory (staging writes tf32 values directly into per-lane
// MMA fragment positions -> mainloop is vectorized LDS.128/LDS.64 + MMA only).
// Double-buffered fragment stages: ONE __syncthreads per k-tile.
// BM=128 fixed; BK=16 (two k8 MMA steps per tile); 256 threads; 2 CTAs/SM.
// ==================================================================================
template <int BN, int EPI, int FUSEA>
__global__ void __launch_bounds__(256, 2)
gemm_tf32(const float* __restrict__ A, const float* __restrict__ A2, int lda,
          const float* __restrict__ W0, const float* __restrict__ W1,
          float* __restrict__ C, int M, int N, int K,
          const float* __restrict__ bias0, const float* __restrict__ bias1,
          long sA_stride, long sC_stride)
{
    constexpr int BM = 128, BK = 16;
    constexpr int G  = BM / 16;      // 8 row-groups
    constexpr int NT = BN / 16;      // 8-col tiles per warp
    constexpr int AV = BM / 64;      // 2
    constexpr int WV = BN / 64;      // 1 or 2

    __shared__ float Afh[2][2][G][8][4][4];   // [stage][s][g][qid][tig'][slot]
    __shared__ float Bfh[2][2][BN][4][2];     // [stage][s][n][tig'][kh]

    const float* W    = blockIdx.z ? W1    : W0;
    const float* bias = blockIdx.z ? bias1 : bias0;
    A += (long)blockIdx.z * sA_stride;
    C += (long)blockIdx.z * sC_stride;

    const int tid  = threadIdx.x;
    const int warp = tid >> 5, lane = tid & 31;
    const int wrow = warp & 3, wcol = warp >> 2;
    const int rowBase = blockIdx.y * BM;
    const int colBase = blockIdx.x * BN;
    const int lr = tid >> 2;           // 0..63
    const int lk = (tid & 3) * 4;      // 0,4,8,12
    const int qid = lane >> 2, tig = lane & 3;

    const int sA  = lk >> 3;           // which k8 step this thread stages
    const int khA = (lk >> 2) & 1;     // k half within step

    float4 pa[AV], pw[WV];

    auto load_g = [&](int k0) {
#pragma unroll
        for (int i = 0; i < AV; i++) {
            int r = rowBase + lr + 64 * i;
            float4 v = *(const float4*)&A[(size_t)r * lda + k0 + lk];
            if (FUSEA) {
                float4 v2 = *(const float4*)&A2[(size_t)(r ^ 2047) * lda + k0 + lk];
                v.x += v2.x; v.y += v2.y; v.z += v2.z; v.w += v2.w;
            }
            pa[i] = v;
        }
#pragma unroll
        for (int i = 0; i < WV; i++) {
            int r = colBase + lr + 64 * i;
            pw[i] = *(const float4*)&W[(size_t)r * K + k0 + lk];
        }
    };

    auto store_s = [&](int stg) {
#pragma unroll
        for (int i = 0; i < AV; i++) {
            int r   = lr + 64 * i;
            int g   = r >> 4;
            int q   = r & 7;
            int slot = ((r >> 3) & 1) + 2 * khA;
            const float* v = &pa[i].x;
#pragma unroll
            for (int j = 0; j < 4; j++) {
                int jj = j ^ (q & 3) ^ (2 * sA);
                Afh[stg][sA][g][q][jj][slot] = f2tf(v[j]);
            }
        }
#pragma unroll
        for (int i = 0; i < WV; i++) {
            int n = lr + 64 * i;
            int cb = ((n & 1) << 1) ^ sA;
            const float* v = &pw[i].x;
#pragma unroll
            for (int j = 0; j < 4; j++) {
                int jj = j ^ cb;
                Bfh[stg][sA][n][jj][khA] = f2tf(v[j]);
            }
        }
    };

    float4 acc[2][NT];
#pragma unroll
    for (int mt = 0; mt < 2; mt++)
#pragma unroll
        for (int nt = 0; nt < NT; nt++) acc[mt][nt] = make_float4(0.f, 0.f, 0.f, 0.f);

    load_g(0);
    store_s(0);
    __syncthreads();

    int buf = 0;
    int k0 = 0;
    for (;;) {
        const bool has_next = (k0 + BK < K);
        if (has_next) load_g(k0 + BK);   // global latency overlapped with MMAs

#pragma unroll
        for (int s = 0; s < 2; s++) {
            const int ptA = tig ^ (qid & 3) ^ (2 * s);
            uint32_t ah[2][4];
#pragma unroll
            for (int mt = 0; mt < 2; mt++) {
                int g = wrow * 2 + mt;
                *(uint4*)ah[mt] = *(const uint4*)&Afh[buf][s][g][qid][ptA][0];
            }
            const int ptB = tig ^ (((qid & 1) << 1) ^ s);
#pragma unroll
            for (int nt = 0; nt < NT; nt++) {
                int n = wcol * (BN / 2) + nt * 8 + qid;
                uint32_t bh[2];
                *(uint2*)bh = *(const uint2*)&Bfh[buf][s][n][ptB][0];
#pragma unroll
                for (int mt = 0; mt < 2; mt++)
                    mma8(acc[mt][nt], ah[mt], bh);
            }
        }

        if (!has_next) break;
        store_s(buf ^ 1);                // write idle stage while peers may still read buf
        __syncthreads();                 // single barrier per k-tile
        buf ^= 1;
        k0 += BK;
    }

    // ---- epilogue ----
#pragma unroll
    for (int mt = 0; mt < 2; mt++) {
#pragma unroll
        for (int nt = 0; nt < NT; nt++) {
            int r0 = rowBase + wrow * 32 + mt * 16 + qid;
            int c  = colBase + wcol * (BN / 2) + nt * 8 + tig * 2;
            float4 v = acc[mt][nt];
            if (EPI == 1) {
                float b0 = bias[c], b1 = bias[c + 1];
                v.x = softplus_f(v.x + b0); v.y = softplus_f(v.y + b1);
                v.z = softplus_f(v.z + b0); v.w = softplus_f(v.w + b1);
            }
            *(float2*)&C[(size_t)r0 * N + c]       = make_float2(v.x, v.y);
            *(float2*)&C[(size_t)(r0 + 8) * N + c] = make_float2(v.z, v.w);
        }
    }
}

// ---------------- depthwise causal conv (K=4) + SiLU, both directions ----------------
__global__ void conv_silu_kernel(const float* __restrict__ cw_f, const float* __restrict__ cb_f,
                                 const float* __restrict__ cw_r, const float* __restrict__ cb_r)
{
    int idx = blockIdx.x * blockDim.x + threadIdx.x;
    if (idx >= 2 * NR * DI) return;
    int d   = idx % DI;
    int r   = (idx / DI) % NR;
    int dir = idx / (DI * NR);
    int b = r / LSEQ, t = r % LSEQ;

    const float* cw = dir ? cw_r : cw_f;
    const float* cb = dir ? cb_r : cb_f;

    float accv = cb[d];
#pragma unroll
    for (int k = 0; k < 4; k++) {
        int tt = t - 3 + k;
        if (tt >= 0) {
            int ts = dir ? (LSEQ - 1 - tt) : tt;
            accv += cw[d * 4 + k] * g_xz[(size_t)(b * LSEQ + ts) * (2 * DI) + d];
        }
    }
    float s = accv / (1.f + __expf(-accv));
    g_xc[dir][(size_t)r * DI + d] = s;
}

// ==================================================================================
// Selective scan: block-cooperative smem staging + cp.async double buffering.
// ==================================================================================
#define SCAN_T 32
#define NCHUNK (LSEQ / SCAN_T)

__device__ __forceinline__ void cpa4(uint32_t s, const void* g) {
    asm volatile("cp.async.ca.shared.global [%0], [%1], 4;" :: "r"(s), "l"(g));
}
__device__ __forceinline__ void cpa_commit() {
    asm volatile("cp.async.commit_group;" ::: "memory");
}
__device__ __forceinline__ void cpa_wait1() {
    asm volatile("cp.async.wait_group 1;" ::: "memory");
}

__global__ void __launch_bounds__(256, 1)
scan_kernel(const float* __restrict__ Alog_f, const float* __restrict__ D_f,
            const float* __restrict__ Alog_r, const float* __restrict__ D_r)
{
    __shared__ float s_dt[2][SCAN_T][16];
    __shared__ float s_x [2][SCAN_T][16];
    __shared__ float s_z [2][SCAN_T][16];
    __shared__ float s_B [2][SCAN_T][16];
    __shared__ float s_C [2][SCAN_T][16];

    const int bx  = blockIdx.x;        // 0..511
    const int dir = bx >> 8;
    const int rem = bx & 255;
    const int b   = rem >> 6;          // 0..3
    const int d0  = (rem & 63) << 4;   // channel group base

    const int tid  = threadIdx.x;
    const int w    = tid >> 5;
    const int lane = tid & 31;
    const int c    = lane >> 4;
    const int n    = lane & 15;
    const int dd   = 2 * w + c;
    const int d    = d0 + dd;

    const float* Alog = dir ? Alog_r : Alog_f;
    const float* Dp   = dir ? D_r   : D_f;
    const float Av = -expf(Alog[d * DS + n]);
    const float Dd = Dp[d];

    const float* dt_base = &g_dt[dir][(size_t)(b * LSEQ) * DI + d0];
    const float* x_base  = &g_xc[dir][(size_t)(b * LSEQ) * DI + d0];
    const float* bc_base = &g_xdbl[dir][(size_t)(b * LSEQ) * 64 + DTR];
    const float* z_base  = &g_xz[(size_t)(b * LSEQ) * (2 * DI) + DI + d0];

    auto load_chunk = [&](int buf, int t0) {
#pragma unroll
        for (int j = 0; j < 2; j++) {
            int e  = j * 256 + tid;
            int tt = e >> 4;
            int k  = e & 15;
            int t  = t0 + tt;
            size_t row = (size_t)t;
            cpa4((uint32_t)__cvta_generic_to_shared(&s_dt[buf][tt][k]), dt_base + row * DI + k);
            cpa4((uint32_t)__cvta_generic_to_shared(&s_x [buf][tt][k]), x_base  + row * DI + k);
            int torig = dir ? (LSEQ - 1 - t) : t;
            cpa4((uint32_t)__cvta_generic_to_shared(&s_z [buf][tt][k]), z_base + (size_t)torig * (2 * DI) + k);
            cpa4((uint32_t)__cvta_generic_to_shared(&s_B [buf][tt][k]), bc_base + row * 64 + k);
            cpa4((uint32_t)__cvta_generic_to_shared(&s_C [buf][tt][k]), bc_base + row * 64 + DS + k);
        }
        cpa_commit();
    };

    load_chunk(0, 0);
    load_chunk(1, SCAN_T);
    cpa_wait1();
    __syncthreads();

    float h = 0.f;
    float* yp = &g_y[dir][(size_t)(b * LSEQ) * DI + d];

    for (int ch = 0; ch < NCHUNK; ch++) {
        const int buf = ch & 1;
#pragma unroll 8
        for (int tt = 0; tt < SCAN_T; tt++) {
            float dtv = s_dt[buf][tt][dd];
            float xv  = s_x [buf][tt][dd];
            float Bv  = s_B [buf][tt][n];
            float Cv  = s_C [buf][tt][n];

            float dA = __expf(dtv * Av);
            h = dA * h + (dtv * xv) * Bv;

            float p = h * Cv;
            p += __shfl_xor_sync(0xffffffffu, p, 8);
            p += __shfl_xor_sync(0xffffffffu, p, 4);
            p += __shfl_xor_sync(0xffffffffu, p, 2);
            p += __shfl_xor_sync(0xffffffffu, p, 1);

            if (n == 0) {
                float zv = s_z[buf][tt][dd];
                float zs = zv / (1.f + __expf(-zv));
                *yp = (p + Dd * xv) * zs;
            }
            yp += DI;
        }
        __syncthreads();
        if (ch + 2 < NCHUNK) load_chunk(buf, (ch + 2) * SCAN_T);
        else                 cpa_commit();
        cpa_wait1();
        __syncthreads();
    }
}

// ---------------- launch ----------------
extern "C" void kernel_launch(void* const* d_in, const int* in_sizes, int n_in,
                              void* d_out, int out_size)
{
    const float* hidden = (const float*)d_in[0];
    const float* W_in   = (const float*)d_in[1];
    const float* W_out  = (const float*)d_in[2];
    const float* cw_f   = (const float*)d_in[3];
    const float* cb_f   = (const float*)d_in[4];
    const float* Wx_f   = (const float*)d_in[5];
    const float* Wdt_f  = (const float*)d_in[6];
    const float* bdt_f  = (const float*)d_in[7];
    const float* Alog_f = (const float*)d_in[8];
    const float* D_f    = (const float*)d_in[9];
    const float* cw_r   = (const float*)d_in[10];
    const float* cb_r   = (const float*)d_in[11];
    const float* Wx_r   = (const float*)d_in[12];
    const float* Wdt_r  = (const float*)d_in[13];
    const float* bdt_r  = (const float*)d_in[14];
    const float* Alog_r = (const float*)d_in[15];
    const float* D_r    = (const float*)d_in[16];
    float* out = (float*)d_out;

    float* xz;   cudaGetSymbolAddress((void**)&xz,   g_xz);
    float* xc;   cudaGetSymbolAddress((void**)&xc,   g_xc);
    float* xdbl; cudaGetSymbolAddress((void**)&xdbl, g_xdbl);
    float* dtb;  cudaGetSymbolAddress((void**)&dtb,  g_dt);
    float* yb;   cudaGetSymbolAddress((void**)&yb,   g_y);

    // 1) xz = hidden @ W_in^T   [8192,512] x [2048,512]^T -> [8192,2048]
    {
        dim3 grid((2 * DI) / 128, NR / 128, 1);
        gemm_tf32<128, 0, 0><<<grid, 256>>>(hidden, nullptr, DM, W_in, nullptr, xz,
                                            NR, 2 * DI, DM, nullptr, nullptr, 0, 0);
    }

    // 2) conv + silu (both dirs)
    {
        int total = 2 * NR * DI;
        conv_silu_kernel<<<(total + 255) / 256, 256>>>(cw_f, cb_f, cw_r, cb_r);
    }

    // 3) x_dbl = xc @ W_x^T  [8192,1024] x [64,1024]^T -> [8192,64]  (dirs batched on z)
    {
        dim3 grid(1, NR / 128, 2);
        gemm_tf32<64, 0, 0><<<grid, 256>>>(xc, nullptr, DI, Wx_f, Wx_r, xdbl,
                                           NR, 64, DI, nullptr, nullptr,
                                           (long)NR * DI, (long)NR * 64);
    }

    // 4) dt = softplus(dt_r @ W_dt^T + b_dt)  [8192,32] x [1024,32]^T -> [8192,1024]
    {
        dim3 grid(DI / 128, NR / 128, 2);
        gemm_tf32<128, 1, 0><<<grid, 256>>>(xdbl, nullptr, 64, Wdt_f, Wdt_r, dtb,
                                            NR, DI, DTR, bdt_f, bdt_r,
                                            (long)NR * 64, (long)NR * DI);
    }

    // 5) selective scan (both dirs): 512 blocks x 8 warps, smem-staged chunks
    scan_kernel<<<512, 256>>>(Alog_f, D_f, Alog_r, D_r);

    // 6+7) out = (y_fwd + reverse(y_rev)) @ W_out^T  [8192,1024] x [512,1024]^T -> [8192,512]
    {
        dim3 grid(DM / 128, NR / 128, 1);
        gemm_tf32<128, 0, 1><<<grid, 256>>>(yb, yb + (size_t)NR * DI, DI, W_out, nullptr, out,
                                            NR, DM, DI, nullptr, nullptr, 0, 0);
    }
}

// round 12
// speedup vs baseline: 5.1341x; 1.1234x over previous
#include <cuda_runtime.h>
#include <math.h>
#include <stdint.h>

// Problem constants
#define BI   4
#define LSEQ 2048
#define DM   512
#define DI   1024      // d_inner
#define DS   16        // d_state
#define DTR  32        // dt_rank
#define NR   (BI*LSEQ) // 8192 rows (b*L flattened)

// ---------------- scratch (static device globals; no allocation) ----------------
__device__ float g_xz  [NR * 2 * DI];   // [row][2048]  x = [:1024], z = [1024:]
__device__ float g_xc  [2][NR * DI];    // conv+silu output per direction (dir-local time)
__device__ float g_xdbl[2][NR * 64];    // [row][64]: dt_r[0:32], B[32:48], C[48:64]
__device__ float g_xdbl_tf[2][NR * 64]; // tf32-rounded copy (dt GEMM A operand)
__device__ float g_dt  [2][NR * DI];    // softplus(dt) per direction
__device__ float g_y   [2][NR * DI];    // scan output per direction (dir-local time)

// pre-rounded (tf32) operands
__device__ float g_hid_tf [NR * DM];
__device__ float g_Win_tf [2 * DI * DM];
__device__ float g_Wx_tf  [2][64 * DI];
__device__ float g_Wdt_tf [2][DI * DTR];
__device__ float g_Wout_tf[DM * DI];

// ---------------- tf32 helpers ----------------
__device__ __forceinline__ float f2tf(float v) {
    uint32_t r; asm("cvt.rna.tf32.f32 %0, %1;" : "=r"(r) : "f"(v));
    return __uint_as_float(r);
}

__device__ __forceinline__ void mma8(float4& d, const uint32_t* a, const uint32_t* b) {
    asm volatile("mma.sync.aligned.m16n8k8.row.col.f32.tf32.tf32.f32 "
                 "{%0,%1,%2,%3}, {%4,%5,%6,%7}, {%8,%9}, {%0,%1,%2,%3};"
                 : "+f"(d.x), "+f"(d.y), "+f"(d.z), "+f"(d.w)
                 : "r"(a[0]), "r"(a[1]), "r"(a[2]), "r"(a[3]), "r"(b[0]), "r"(b[1]));
}

__device__ __forceinline__ float softplus_f(float t) {
    return (t > 20.f) ? t : log1pf(expf(t));
}

// ---------------- one-time tf32 rounding of an array (n divisible by 4) ----------------
__global__ void round_tf_kernel(const float* __restrict__ src, float* __restrict__ dst, int n)
{
    int i = (blockIdx.x * blockDim.x + threadIdx.x) * 4;
    if (i < n) {
        float4 v = *(const float4*)&src[i];
        v.x = f2tf(v.x); v.y = f2tf(v.y); v.z = f2tf(v.z); v.w = f2tf(v.w);
        *(float4*)&dst[i] = v;
    }
}

// ==================================================================================
// Single-pass tf32 tensor-core GEMM:  C[M,N] = A[M,K] @ W[N,K]^T
// Fragment-order shared memory; double-buffered stages; ONE __syncthreads per tile.
// W is ALWAYS pre-rounded tf32 (no cvt). A cvt only if CVT_A (FUSEA sum / raw fp32 A).
// DUAL: epilogue additionally writes tf32-rounded copy to C2.
// ==================================================================================
template <int BN, int EPI, int FUSEA, int CVT_A, int DUAL>
__global__ void __launch_bounds__(256, 2)
gemm_tf32(const float* __restrict__ A, const float* __restrict__ A2, int lda,
          const float* __restrict__ W0, const float* __restrict__ W1,
          float* __restrict__ C, int M, int N, int K,
          const float* __restrict__ bias0, const float* __restrict__ bias1,
          long sA_stride, long sC_stride, float* __restrict__ C2)
{
    constexpr int BM = 128, BK = 16;
    constexpr int G  = BM / 16;      // 8 row-groups
    constexpr int NT = BN / 16;      // 8-col tiles per warp
    constexpr int AV = BM / 64;      // 2
    constexpr int WV = BN / 64;      // 1 or 2

    __shared__ float Afh[2][2][G][8][4][4];   // [stage][s][g][qid][tig'][slot]
    __shared__ float Bfh[2][2][BN][4][2];     // [stage][s][n][tig'][kh]

    const float* W    = blockIdx.z ? W1    : W0;
    const float* bias = blockIdx.z ? bias1 : bias0;
    A += (long)blockIdx.z * sA_stride;
    C += (long)blockIdx.z * sC_stride;
    if (DUAL) C2 += (long)blockIdx.z * sC_stride;

    const int tid  = threadIdx.x;
    const int warp = tid >> 5, lane = tid & 31;
    const int wrow = warp & 3, wcol = warp >> 2;
    const int rowBase = blockIdx.y * BM;
    const int colBase = blockIdx.x * BN;
    const int lr = tid >> 2;           // 0..63
    const int lk = (tid & 3) * 4;      // 0,4,8,12
    const int qid = lane >> 2, tig = lane & 3;

    const int sA  = lk >> 3;           // which k8 step this thread stages
    const int khA = (lk >> 2) & 1;     // k half within step

    float4 pa[AV], pw[WV];

    auto load_g = [&](int k0) {
#pragma unroll
        for (int i = 0; i < AV; i++) {
            int r = rowBase + lr + 64 * i;
            float4 v = *(const float4*)&A[(size_t)r * lda + k0 + lk];
            if (FUSEA) {
                float4 v2 = *(const float4*)&A2[(size_t)(r ^ 2047) * lda + k0 + lk];
                v.x += v2.x; v.y += v2.y; v.z += v2.z; v.w += v2.w;
            }
            pa[i] = v;
        }
#pragma unroll
        for (int i = 0; i < WV; i++) {
            int r = colBase + lr + 64 * i;
            pw[i] = *(const float4*)&W[(size_t)r * K + k0 + lk];
        }
    };

    auto store_s = [&](int stg) {
#pragma unroll
        for (int i = 0; i < AV; i++) {
            int r   = lr + 64 * i;
            int g   = r >> 4;
            int q   = r & 7;
            int slot = ((r >> 3) & 1) + 2 * khA;
            const float* v = &pa[i].x;
#pragma unroll
            for (int j = 0; j < 4; j++) {
                int jj = j ^ (q & 3) ^ (2 * sA);
                Afh[stg][sA][g][q][jj][slot] = CVT_A ? f2tf(v[j]) : v[j];
            }
        }
#pragma unroll
        for (int i = 0; i < WV; i++) {
            int n = lr + 64 * i;
            int cb = ((n & 1) << 1) ^ sA;
            const float* v = &pw[i].x;
#pragma unroll
            for (int j = 0; j < 4; j++) {
                int jj = j ^ cb;
                Bfh[stg][sA][n][jj][khA] = v[j];   // W pre-rounded: no cvt
            }
        }
    };

    float4 acc[2][NT];
#pragma unroll
    for (int mt = 0; mt < 2; mt++)
#pragma unroll
        for (int nt = 0; nt < NT; nt++) acc[mt][nt] = make_float4(0.f, 0.f, 0.f, 0.f);

    load_g(0);
    store_s(0);
    __syncthreads();

    int buf = 0;
    int k0 = 0;
    for (;;) {
        const bool has_next = (k0 + BK < K);
        if (has_next) load_g(k0 + BK);   // global latency overlapped with MMAs

#pragma unroll
        for (int s = 0; s < 2; s++) {
            const int ptA = tig ^ (qid & 3) ^ (2 * s);
            uint32_t ah[2][4];
#pragma unroll
            for (int mt = 0; mt < 2; mt++) {
                int g = wrow * 2 + mt;
                *(uint4*)ah[mt] = *(const uint4*)&Afh[buf][s][g][qid][ptA][0];
            }
            const int ptB = tig ^ (((qid & 1) << 1) ^ s);
#pragma unroll
            for (int nt = 0; nt < NT; nt++) {
                int n = wcol * (BN / 2) + nt * 8 + qid;
                uint32_t bh[2];
                *(uint2*)bh = *(const uint2*)&Bfh[buf][s][n][ptB][0];
#pragma unroll
                for (int mt = 0; mt < 2; mt++)
                    mma8(acc[mt][nt], ah[mt], bh);
            }
        }

        if (!has_next) break;
        store_s(buf ^ 1);
        __syncthreads();                 // single barrier per k-tile
        buf ^= 1;
        k0 += BK;
    }

    // ---- epilogue ----
#pragma unroll
    for (int mt = 0; mt < 2; mt++) {
#pragma unroll
        for (int nt = 0; nt < NT; nt++) {
            int r0 = rowBase + wrow * 32 + mt * 16 + qid;
            int c  = colBase + wcol * (BN / 2) + nt * 8 + tig * 2;
            float4 v = acc[mt][nt];
            if (EPI == 1) {
                float b0 = bias[c], b1 = bias[c + 1];
                v.x = softplus_f(v.x + b0); v.y = softplus_f(v.y + b1);
                v.z = softplus_f(v.z + b0); v.w = softplus_f(v.w + b1);
            }
            *(float2*)&C[(size_t)r0 * N + c]       = make_float2(v.x, v.y);
            *(float2*)&C[(size_t)(r0 + 8) * N + c] = make_float2(v.z, v.w);
            if (DUAL) {
                *(float2*)&C2[(size_t)r0 * N + c]       = make_float2(f2tf(v.x), f2tf(v.y));
                *(float2*)&C2[(size_t)(r0 + 8) * N + c] = make_float2(f2tf(v.z), f2tf(v.w));
            }
        }
    }
}

// ---------------- depthwise causal conv (K=4) + SiLU, both directions ----------------
__global__ void conv_silu_kernel(const float* __restrict__ cw_f, const float* __restrict__ cb_f,
                                 const float* __restrict__ cw_r, const float* __restrict__ cb_r)
{
    int idx = blockIdx.x * blockDim.x + threadIdx.x;
    if (idx >= 2 * NR * DI) return;
    int d   = idx % DI;
    int r   = (idx / DI) % NR;
    int dir = idx / (DI * NR);
    int b = r / LSEQ, t = r % LSEQ;

    const float* cw = dir ? cw_r : cw_f;
    const float* cb = dir ? cb_r : cb_f;

    float accv = cb[d];
#pragma unroll
    for (int k = 0; k < 4; k++) {
        int tt = t - 3 + k;
        if (tt >= 0) {
            int ts = dir ? (LSEQ - 1 - tt) : tt;
            accv += cw[d * 4 + k] * g_xz[(size_t)(b * LSEQ + ts) * (2 * DI) + d];
        }
    }
    float s = accv / (1.f + __expf(-accv));
    g_xc[dir][(size_t)r * DI + d] = s;
}

// ==================================================================================
// Selective scan v3: warp = 4 channels x 8 lanes, 2 states per lane.
// 256 blocks; block = (dir, b, 32-channel group); 8 warps x 4 channels = 32 channels.
// Chunks of SCAN_T=32 steps staged via 16B cp.async, double-buffered.
// ==================================================================================
#define SCAN_T 32
#define NCHUNK (LSEQ / SCAN_T)

__device__ __forceinline__ void cpa16(void* s, const void* g) {
    uint32_t sa = (uint32_t)__cvta_generic_to_shared(s);
    asm volatile("cp.async.ca.shared.global [%0], [%1], 16;" :: "r"(sa), "l"(g));
}
__device__ __forceinline__ void cpa_commit() {
    asm volatile("cp.async.commit_group;" ::: "memory");
}
__device__ __forceinline__ void cpa_wait1() {
    asm volatile("cp.async.wait_group 1;" ::: "memory");
}

__global__ void __launch_bounds__(256, 2)
scan_kernel(const float* __restrict__ Alog_f, const float* __restrict__ D_f,
            const float* __restrict__ Alog_r, const float* __restrict__ D_r)
{
    __shared__ __align__(16) float s_dt[2][SCAN_T][32];
    __shared__ __align__(16) float s_x [2][SCAN_T][32];
    __shared__ __align__(16) float s_z [2][SCAN_T][32];
    __shared__ __align__(16) float s_B [2][SCAN_T][16];
    __shared__ __align__(16) float s_C [2][SCAN_T][16];

    const int bx  = blockIdx.x;        // 0..255
    const int dir = bx >> 7;
    const int rem = bx & 127;
    const int b   = rem >> 5;          // 0..3
    const int d0  = (rem & 31) << 5;   // 32-channel group base

    const int tid  = threadIdx.x;
    const int w    = tid >> 5;
    const int lane = tid & 31;
    const int cc   = lane >> 3;        // channel within warp (0..3)
    const int j    = lane & 7;         // state-pair index (0..7)
    const int ch   = 4 * w + cc;       // local channel 0..31
    const int d    = d0 + ch;

    const float* Alog = dir ? Alog_r : Alog_f;
    const float* Dp   = dir ? D_r   : D_f;
    const float Av0 = -expf(Alog[d * DS + 2 * j]);
    const float Av1 = -expf(Alog[d * DS + 2 * j + 1]);
    const float Dd  = Dp[d];

    const float* dt_base = &g_dt[dir][(size_t)(b * LSEQ) * DI + d0];
    const float* x_base  = &g_xc[dir][(size_t)(b * LSEQ) * DI + d0];
    const float* bc_base = &g_xdbl[dir][(size_t)(b * LSEQ) * 64 + DTR];
    const float* z_base  = &g_xz[(size_t)(b * LSEQ) * (2 * DI) + DI + d0];

    // chunk load: dt/x/z 1024 floats each (256 x 16B), B and C 512 floats each
    const int ltt = tid >> 3, lq4 = (tid & 7) * 4;         // dt/x/z mapping
    const int hbc = tid >> 7;                              // 0 -> B, 1 -> C
    const int lt2 = (tid & 127) >> 2, lk4 = (tid & 3) * 4; // B/C mapping

    auto load_chunk = [&](int buf, int t0) {
        size_t row = (size_t)(t0 + ltt);
        cpa16(&s_dt[buf][ltt][lq4], dt_base + row * DI + lq4);
        cpa16(&s_x [buf][ltt][lq4], x_base  + row * DI + lq4);
        int torig = dir ? (LSEQ - 1 - (t0 + ltt)) : (t0 + ltt);
        cpa16(&s_z [buf][ltt][lq4], z_base + (size_t)torig * (2 * DI) + lq4);
        size_t row2 = (size_t)(t0 + lt2);
        if (hbc == 0) cpa16(&s_B[buf][lt2][lk4], bc_base + row2 * 64 + lk4);
        else          cpa16(&s_C[buf][lt2][lk4], bc_base + row2 * 64 + DS + lk4);
        cpa_commit();
    };

    load_chunk(0, 0);
    load_chunk(1, SCAN_T);
    cpa_wait1();
    __syncthreads();

    float h0 = 0.f, h1 = 0.f;
    float* yp = &g_y[dir][(size_t)(b * LSEQ) * DI + d];

    for (int chk = 0; chk < NCHUNK; chk++) {
        const int buf = chk & 1;
#pragma unroll 8
        for (int tt = 0; tt < SCAN_T; tt++) {
            float dtv = s_dt[buf][tt][ch];
            float xv  = s_x [buf][tt][ch];
            float2 Bv = *(const float2*)&s_B[buf][tt][2 * j];
            float2 Cv = *(const float2*)&s_C[buf][tt][2 * j];

            float u = dtv * xv;
            h0 = __expf(dtv * Av0) * h0 + u * Bv.x;
            h1 = __expf(dtv * Av1) * h1 + u * Bv.y;

            float p = h0 * Cv.x + h1 * Cv.y;
            p += __shfl_xor_sync(0xffffffffu, p, 4);
            p += __shfl_xor_sync(0xffffffffu, p, 2);
            p += __shfl_xor_sync(0xffffffffu, p, 1);

            if (j == 0) {
                float zv = s_z[buf][tt][ch];
                float zs = zv / (1.f + __expf(-zv));
                *yp = (p + Dd * xv) * zs;
            }
            yp += DI;
        }
        __syncthreads();
        if (chk + 2 < NCHUNK) load_chunk(buf, (chk + 2) * SCAN_T);
        else                  cpa_commit();
        cpa_wait1();
        __syncthreads();
    }
}

// ---------------- launch ----------------
extern "C" void kernel_launch(void* const* d_in, const int* in_sizes, int n_in,
                              void* d_out, int out_size)
{
    const float* hidden = (const float*)d_in[0];
    const float* W_in   = (const float*)d_in[1];
    const float* W_out  = (const float*)d_in[2];
    const float* cw_f   = (const float*)d_in[3];
    const float* cb_f   = (const float*)d_in[4];
    const float* Wx_f   = (const float*)d_in[5];
    const float* Wdt_f  = (const float*)d_in[6];
    const float* bdt_f  = (const float*)d_in[7];
    const float* Alog_f = (const float*)d_in[8];
    const float* D_f    = (const float*)d_in[9];
    const float* cw_r   = (const float*)d_in[10];
    const float* cb_r   = (const float*)d_in[11];
    const float* Wx_r   = (const float*)d_in[12];
    const float* Wdt_r  = (const float*)d_in[13];
    const float* bdt_r  = (const float*)d_in[14];
    const float* Alog_r = (const float*)d_in[15];
    const float* D_r    = (const float*)d_in[16];
    float* out = (float*)d_out;

    float* xz;      cudaGetSymbolAddress((void**)&xz,      g_xz);
    float* xc;      cudaGetSymbolAddress((void**)&xc,      g_xc);
    float* xdbl;    cudaGetSymbolAddress((void**)&xdbl,    g_xdbl);
    float* xdbl_tf; cudaGetSymbolAddress((void**)&xdbl_tf, g_xdbl_tf);
    float* dtb;     cudaGetSymbolAddress((void**)&dtb,     g_dt);
    float* yb;      cudaGetSymbolAddress((void**)&yb,      g_y);
    float* hid_tf;  cudaGetSymbolAddress((void**)&hid_tf,  g_hid_tf);
    float* Win_tf;  cudaGetSymbolAddress((void**)&Win_tf,  g_Win_tf);
    float* Wx_tf;   cudaGetSymbolAddress((void**)&Wx_tf,   g_Wx_tf);
    float* Wdt_tf;  cudaGetSymbolAddress((void**)&Wdt_tf,  g_Wdt_tf);
    float* Wout_tf; cudaGetSymbolAddress((void**)&Wout_tf, g_Wout_tf);

    // 0) pre-round weights + hidden to tf32 (one-time per launch; ~12us of copies)
    auto rnd = [&](const float* s, float* dst, int n) {
        round_tf_kernel<<<(n / 4 + 255) / 256, 256>>>(s, dst, n);
    };
    rnd(hidden, hid_tf,  NR * DM);
    rnd(W_in,   Win_tf,  2 * DI * DM);
    rnd(Wx_f,   Wx_tf,            64 * DI);
    rnd(Wx_r,   Wx_tf + 64 * DI,  64 * DI);
    rnd(Wdt_f,  Wdt_tf,             DI * DTR);
    rnd(Wdt_r,  Wdt_tf + DI * DTR,  DI * DTR);
    rnd(W_out,  Wout_tf, DM * DI);

    // 1) xz = hidden @ W_in^T   [8192,512] x [2048,512]^T -> [8192,2048]
    {
        dim3 grid((2 * DI) / 128, NR / 128, 1);
        gemm_tf32<128, 0, 0, 0, 0><<<grid, 256>>>(hid_tf, nullptr, DM, Win_tf, nullptr, xz,
                                                  NR, 2 * DI, DM, nullptr, nullptr, 0, 0, nullptr);
    }

    // 2) conv + silu (both dirs)
    {
        int total = 2 * NR * DI;
        conv_silu_kernel<<<(total + 255) / 256, 256>>>(cw_f, cb_f, cw_r, cb_r);
    }

    // 3) x_dbl = xc @ W_x^T  [8192,1024] x [64,1024]^T -> [8192,64]  (dirs batched on z)
    //    DUAL store: fp32 for the scan, tf32-rounded for the dt GEMM
    {
        dim3 grid(1, NR / 128, 2);
        gemm_tf32<64, 0, 0, 1, 1><<<grid, 256>>>(xc, nullptr, DI, Wx_tf, Wx_tf + 64 * DI, xdbl,
                                                 NR, 64, DI, nullptr, nullptr,
                                                 (long)NR * DI, (long)NR * 64, xdbl_tf);
    }

    // 4) dt = softplus(dt_r @ W_dt^T + b_dt)  [8192,32] x [1024,32]^T -> [8192,1024]
    {
        dim3 grid(DI / 128, NR / 128, 2);
        gemm_tf32<128, 1, 0, 0, 0><<<grid, 256>>>(xdbl_tf, nullptr, 64, Wdt_tf, Wdt_tf + DI * DTR, dtb,
                                                  NR, DI, DTR, bdt_f, bdt_r,
                                                  (long)NR * 64, (long)NR * DI, nullptr);
    }

    // 5) selective scan (both dirs): 256 blocks x 8 warps, 4 channels/warp
    scan_kernel<<<256, 256>>>(Alog_f, D_f, Alog_r, D_r);

    // 6+7) out = (y_fwd + reverse(y_rev)) @ W_out^T  [8192,1024] x [512,1024]^T -> [8192,512]
    {
        dim3 grid(DM / 128, NR / 128, 1);
        gemm_tf32<128, 0, 1, 1, 0><<<grid, 256>>>(yb, yb + (size_t)NR * DI, DI, Wout_tf, nullptr, out,
                                                  NR, DM, DI, nullptr, nullptr, 0, 0, nullptr);
    }
}

// round 13
// speedup vs baseline: 5.3972x; 1.0512x over previous
#include <cuda_runtime.h>
#include <math.h>
#include <stdint.h>

// Problem constants
#define BI   4
#define LSEQ 2048
#define DM   512
#define DI   1024      // d_inner
#define DS   16        // d_state
#define DTR  32        // dt_rank
#define NR   (BI*LSEQ) // 8192 rows (b*L flattened)

// ---------------- scratch (static device globals; no allocation) ----------------
__device__ float g_xz  [NR * 2 * DI];   // [row][2048]  x = [:1024], z = [1024:]
__device__ float g_xc  [2][NR * DI];    // conv+silu output per direction (dir-local time)
__device__ float g_xdbl[2][NR * 64];    // [row][64]: dt_r[0:32], B[32:48], C[48:64]
__device__ float g_xdbl_tf[2][NR * 64]; // tf32-rounded copy (dt GEMM A operand)
__device__ float g_dt  [2][NR * DI];    // softplus(dt) per direction
__device__ float g_y   [2][NR * DI];    // scan output per direction (dir-local time)

// pre-rounded (tf32) operands
__device__ float g_hid_tf [NR * DM];
__device__ float g_Win_tf [2 * DI * DM];
__device__ float g_Wx_tf  [2][64 * DI];
__device__ float g_Wdt_tf [2][DI * DTR];
__device__ float g_Wout_tf[DM * DI];

// ---------------- tf32 helpers ----------------
__device__ __forceinline__ float f2tf(float v) {
    uint32_t r; asm("cvt.rna.tf32.f32 %0, %1;" : "=r"(r) : "f"(v));
    return __uint_as_float(r);
}

__device__ __forceinline__ void mma8(float4& d, const uint32_t* a, const uint32_t* b) {
    asm volatile("mma.sync.aligned.m16n8k8.row.col.f32.tf32.tf32.f32 "
                 "{%0,%1,%2,%3}, {%4,%5,%6,%7}, {%8,%9}, {%0,%1,%2,%3};"
                 : "+f"(d.x), "+f"(d.y), "+f"(d.z), "+f"(d.w)
                 : "r"(a[0]), "r"(a[1]), "r"(a[2]), "r"(a[3]), "r"(b[0]), "r"(b[1]));
}

__device__ __forceinline__ float softplus_f(float t) {
    return (t > 20.f) ? t : log1pf(expf(t));
}

// ---------------- ONE fused tf32 pre-rounding kernel (all operands) ----------------
__global__ void round_all_kernel(const float* __restrict__ hidden,
                                 const float* __restrict__ W_in,
                                 const float* __restrict__ W_out,
                                 const float* __restrict__ Wx_f, const float* __restrict__ Wx_r,
                                 const float* __restrict__ Wdt_f, const float* __restrict__ Wdt_r)
{
    // segment boundaries in float4 units (compile-time)
    constexpr int S0 = NR * DM / 4;              // hidden
    constexpr int S1 = S0 + 2 * DI * DM / 4;     // W_in
    constexpr int S2 = S1 + 64 * DI / 4;         // Wx_f
    constexpr int S3 = S2 + 64 * DI / 4;         // Wx_r
    constexpr int S4 = S3 + DI * DTR / 4;        // Wdt_f
    constexpr int S5 = S4 + DI * DTR / 4;        // Wdt_r
    constexpr int S6 = S5 + DM * DI / 4;         // W_out

    int i = blockIdx.x * blockDim.x + threadIdx.x;
    if (i >= S6) return;

    const float* src; float* dst; int base;
    if      (i < S0) { src = hidden; dst = g_hid_tf;            base = 0;  }
    else if (i < S1) { src = W_in;   dst = g_Win_tf;            base = S0; }
    else if (i < S2) { src = Wx_f;   dst = g_Wx_tf[0];          base = S1; }
    else if (i < S3) { src = Wx_r;   dst = g_Wx_tf[1];          base = S2; }
    else if (i < S4) { src = Wdt_f;  dst = g_Wdt_tf[0];         base = S3; }
    else if (i < S5) { src = Wdt_r;  dst = g_Wdt_tf[1];         base = S4; }
    else             { src = W_out;  dst = g_Wout_tf;           base = S5; }

    int off = (i - base) * 4;
    float4 v = *(const float4*)&src[off];
    v.x = f2tf(v.x); v.y = f2tf(v.y); v.z = f2tf(v.z); v.w = f2tf(v.w);
    *(float4*)&dst[off] = v;
}

// ==================================================================================
// Single-pass tf32 tensor-core GEMM:  C[M,N] = A[M,K] @ W[N,K]^T
// Fragment-order shared memory; double-buffered stages; ONE __syncthreads per tile.
// W is ALWAYS pre-rounded tf32 (no cvt). A cvt only if CVT_A.
// DUAL: epilogue additionally writes tf32-rounded copy to C2.
// ==================================================================================
template <int BN, int EPI, int FUSEA, int CVT_A, int DUAL>
__global__ void __launch_bounds__(256, 2)
gemm_tf32(const float* __restrict__ A, const float* __restrict__ A2, int lda,
          const float* __restrict__ W0, const float* __restrict__ W1,
          float* __restrict__ C, int M, int N, int K,
          const float* __restrict__ bias0, const float* __restrict__ bias1,
          long sA_stride, long sC_stride, float* __restrict__ C2)
{
    constexpr int BM = 128, BK = 16;
    constexpr int G  = BM / 16;
    constexpr int NT = BN / 16;
    constexpr int AV = BM / 64;
    constexpr int WV = BN / 64;

    __shared__ float Afh[2][2][G][8][4][4];   // [stage][s][g][qid][tig'][slot]
    __shared__ float Bfh[2][2][BN][4][2];     // [stage][s][n][tig'][kh]

    const float* W    = blockIdx.z ? W1    : W0;
    const float* bias = blockIdx.z ? bias1 : bias0;
    A += (long)blockIdx.z * sA_stride;
    C += (long)blockIdx.z * sC_stride;
    if (DUAL) C2 += (long)blockIdx.z * sC_stride;

    const int tid  = threadIdx.x;
    const int warp = tid >> 5, lane = tid & 31;
    const int wrow = warp & 3, wcol = warp >> 2;
    const int rowBase = blockIdx.y * BM;
    const int colBase = blockIdx.x * BN;
    const int lr = tid >> 2;
    const int lk = (tid & 3) * 4;
    const int qid = lane >> 2, tig = lane & 3;

    const int sA  = lk >> 3;
    const int khA = (lk >> 2) & 1;

    float4 pa[AV], pw[WV];

    auto load_g = [&](int k0) {
#pragma unroll
        for (int i = 0; i < AV; i++) {
            int r = rowBase + lr + 64 * i;
            float4 v = *(const float4*)&A[(size_t)r * lda + k0 + lk];
            if (FUSEA) {
                float4 v2 = *(const float4*)&A2[(size_t)(r ^ 2047) * lda + k0 + lk];
                v.x += v2.x; v.y += v2.y; v.z += v2.z; v.w += v2.w;
            }
            pa[i] = v;
        }
#pragma unroll
        for (int i = 0; i < WV; i++) {
            int r = colBase + lr + 64 * i;
            pw[i] = *(const float4*)&W[(size_t)r * K + k0 + lk];
        }
    };

    auto store_s = [&](int stg) {
#pragma unroll
        for (int i = 0; i < AV; i++) {
            int r   = lr + 64 * i;
            int g   = r >> 4;
            int q   = r & 7;
            int slot = ((r >> 3) & 1) + 2 * khA;
            const float* v = &pa[i].x;
#pragma unroll
            for (int j = 0; j < 4; j++) {
                int jj = j ^ (q & 3) ^ (2 * sA);
                Afh[stg][sA][g][q][jj][slot] = CVT_A ? f2tf(v[j]) : v[j];
            }
        }
#pragma unroll
        for (int i = 0; i < WV; i++) {
            int n = lr + 64 * i;
            int cb = ((n & 1) << 1) ^ sA;
            const float* v = &pw[i].x;
#pragma unroll
            for (int j = 0; j < 4; j++) {
                int jj = j ^ cb;
                Bfh[stg][sA][n][jj][khA] = v[j];
            }
        }
    };

    float4 acc[2][NT];
#pragma unroll
    for (int mt = 0; mt < 2; mt++)
#pragma unroll
        for (int nt = 0; nt < NT; nt++) acc[mt][nt] = make_float4(0.f, 0.f, 0.f, 0.f);

    load_g(0);
    store_s(0);
    __syncthreads();

    int buf = 0;
    int k0 = 0;
    for (;;) {
        const bool has_next = (k0 + BK < K);
        if (has_next) load_g(k0 + BK);

#pragma unroll
        for (int s = 0; s < 2; s++) {
            const int ptA = tig ^ (qid & 3) ^ (2 * s);
            uint32_t ah[2][4];
#pragma unroll
            for (int mt = 0; mt < 2; mt++) {
                int g = wrow * 2 + mt;
                *(uint4*)ah[mt] = *(const uint4*)&Afh[buf][s][g][qid][ptA][0];
            }
            const int ptB = tig ^ (((qid & 1) << 1) ^ s);
#pragma unroll
            for (int nt = 0; nt < NT; nt++) {
                int n = wcol * (BN / 2) + nt * 8 + qid;
                uint32_t bh[2];
                *(uint2*)bh = *(const uint2*)&Bfh[buf][s][n][ptB][0];
#pragma unroll
                for (int mt = 0; mt < 2; mt++)
                    mma8(acc[mt][nt], ah[mt], bh);
            }
        }

        if (!has_next) break;
        store_s(buf ^ 1);
        __syncthreads();
        buf ^= 1;
        k0 += BK;
    }

    // ---- epilogue ----
#pragma unroll
    for (int mt = 0; mt < 2; mt++) {
#pragma unroll
        for (int nt = 0; nt < NT; nt++) {
            int r0 = rowBase + wrow * 32 + mt * 16 + qid;
            int c  = colBase + wcol * (BN / 2) + nt * 8 + tig * 2;
            float4 v = acc[mt][nt];
            if (EPI == 1) {
                float b0 = bias[c], b1 = bias[c + 1];
                v.x = softplus_f(v.x + b0); v.y = softplus_f(v.y + b1);
                v.z = softplus_f(v.z + b0); v.w = softplus_f(v.w + b1);
            }
            *(float2*)&C[(size_t)r0 * N + c]       = make_float2(v.x, v.y);
            *(float2*)&C[(size_t)(r0 + 8) * N + c] = make_float2(v.z, v.w);
            if (DUAL) {
                *(float2*)&C2[(size_t)r0 * N + c]       = make_float2(f2tf(v.x), f2tf(v.y));
                *(float2*)&C2[(size_t)(r0 + 8) * N + c] = make_float2(f2tf(v.z), f2tf(v.w));
            }
        }
    }
}

// ---------------- depthwise causal conv (K=4) + SiLU, both directions ----------------
__global__ void conv_silu_kernel(const float* __restrict__ cw_f, const float* __restrict__ cb_f,
                                 const float* __restrict__ cw_r, const float* __restrict__ cb_r)
{
    int idx = blockIdx.x * blockDim.x + threadIdx.x;
    if (idx >= 2 * NR * DI) return;
    int d   = idx % DI;
    int r   = (idx / DI) % NR;
    int dir = idx / (DI * NR);
    int b = r / LSEQ, t = r % LSEQ;

    const float* cw = dir ? cw_r : cw_f;
    const float* cb = dir ? cb_r : cb_f;

    float accv = cb[d];
#pragma unroll
    for (int k = 0; k < 4; k++) {
        int tt = t - 3 + k;
        if (tt >= 0) {
            int ts = dir ? (LSEQ - 1 - tt) : tt;
            accv += cw[d * 4 + k] * g_xz[(size_t)(b * LSEQ + ts) * (2 * DI) + d];
        }
    }
    float s = accv / (1.f + __expf(-accv));
    g_xc[dir][(size_t)r * DI + d] = s;
}

// ==================================================================================
// Selective scan v4: warp = 4 channels x 8 lanes, 2 states per lane.
// 256 blocks; block = (dir, b, 32-channel group); SCAN_T=64 chunks, TRIPLE buffered:
// one __syncthreads per chunk (write target (ch+2)%3 never collides with readers).
// ==================================================================================
#define SCAN_T 64
#define NCHUNK (LSEQ / SCAN_T)

__device__ __forceinline__ void cpa16(void* s, const void* g) {
    uint32_t sa = (uint32_t)__cvta_generic_to_shared(s);
    asm volatile("cp.async.ca.shared.global [%0], [%1], 16;" :: "r"(sa), "l"(g));
}
__device__ __forceinline__ void cpa_commit() {
    asm volatile("cp.async.commit_group;" ::: "memory");
}
__device__ __forceinline__ void cpa_wait1() {
    asm volatile("cp.async.wait_group 1;" ::: "memory");
}

__global__ void __launch_bounds__(256, 2)
scan_kernel(const float* __restrict__ Alog_f, const float* __restrict__ D_f,
            const float* __restrict__ Alog_r, const float* __restrict__ D_r)
{
    __shared__ __align__(16) float s_dt[3][SCAN_T][32];
    __shared__ __align__(16) float s_x [3][SCAN_T][32];
    __shared__ __align__(16) float s_z [3][SCAN_T][32];
    __shared__ __align__(16) float s_B [3][SCAN_T][16];
    __shared__ __align__(16) float s_C [3][SCAN_T][16];

    const int bx  = blockIdx.x;        // 0..255
    const int dir = bx >> 7;
    const int rem = bx & 127;
    const int b   = rem >> 5;          // 0..3
    const int d0  = (rem & 31) << 5;   // 32-channel group base

    const int tid  = threadIdx.x;
    const int w    = tid >> 5;
    const int lane = tid & 31;
    const int cc   = lane >> 3;        // channel within warp (0..3)
    const int j    = lane & 7;         // state-pair index (0..7)
    const int ch   = 4 * w + cc;       // local channel 0..31
    const int d    = d0 + ch;

    const float* Alog = dir ? Alog_r : Alog_f;
    const float* Dp   = dir ? D_r   : D_f;
    const float Av0 = -expf(Alog[d * DS + 2 * j]);
    const float Av1 = -expf(Alog[d * DS + 2 * j + 1]);
    const float Dd  = Dp[d];

    const float* dt_base = &g_dt[dir][(size_t)(b * LSEQ) * DI + d0];
    const float* x_base  = &g_xc[dir][(size_t)(b * LSEQ) * DI + d0];
    const float* bc_base = &g_xdbl[dir][(size_t)(b * LSEQ) * 64 + DTR];
    const float* z_base  = &g_xz[(size_t)(b * LSEQ) * (2 * DI) + DI + d0];

    // chunk load (SCAN_T=64): dt/x/z: 512 float4 each -> 2 per thread.
    // B and C: 256 float4 each; threads 0-127 load B (2 each), 128-255 load C (2 each).
    const int hbc = tid >> 7;          // 0 -> B, 1 -> C
    const int tl  = tid & 127;

    auto load_chunk = [&](int buf, int t0) {
#pragma unroll
        for (int q = 0; q < 2; q++) {
            int e  = q * 256 + tid;        // 0..511
            int tt = e >> 3;               // 0..63
            int lq4 = (e & 7) * 4;         // 0..28
            size_t row = (size_t)(t0 + tt);
            cpa16(&s_dt[buf][tt][lq4], dt_base + row * DI + lq4);
            cpa16(&s_x [buf][tt][lq4], x_base  + row * DI + lq4);
            int torig = dir ? (LSEQ - 1 - (t0 + tt)) : (t0 + tt);
            cpa16(&s_z [buf][tt][lq4], z_base + (size_t)torig * (2 * DI) + lq4);

            int e2  = q * 128 + tl;        // 0..255
            int tt2 = e2 >> 2;             // 0..63
            int lk4 = (e2 & 3) * 4;        // 0..12
            size_t row2 = (size_t)(t0 + tt2);
            if (hbc == 0) cpa16(&s_B[buf][tt2][lk4], bc_base + row2 * 64 + lk4);
            else          cpa16(&s_C[buf][tt2][lk4], bc_base + row2 * 64 + DS + lk4);
        }
        cpa_commit();
    };

    load_chunk(0, 0);
    load_chunk(1, SCAN_T);
    cpa_wait1();
    __syncthreads();

    float h0 = 0.f, h1 = 0.f;
    float* yp = &g_y[dir][(size_t)(b * LSEQ) * DI + d];

    int buf = 0;
    for (int chk = 0; chk < NCHUNK; chk++) {
#pragma unroll 8
        for (int tt = 0; tt < SCAN_T; tt++) {
            float dtv = s_dt[buf][tt][ch];
            float xv  = s_x [buf][tt][ch];
            float2 Bv = *(const float2*)&s_B[buf][tt][2 * j];
            float2 Cv = *(const float2*)&s_C[buf][tt][2 * j];

            float u = dtv * xv;
            h0 = __expf(dtv * Av0) * h0 + u * Bv.x;
            h1 = __expf(dtv * Av1) * h1 + u * Bv.y;

            float p = h0 * Cv.x + h1 * Cv.y;
            p += __shfl_xor_sync(0xffffffffu, p, 4);
            p += __shfl_xor_sync(0xffffffffu, p, 2);
            p += __shfl_xor_sync(0xffffffffu, p, 1);

            if (j == 0) {
                float zv = s_z[buf][tt][ch];
                float zs = zv / (1.f + __expf(-zv));
                *yp = (p + Dd * xv) * zs;
            }
            yp += DI;
        }
        // triple buffer: write target (chk+2)%3 is disjoint from buffers being read
        if (chk + 2 < NCHUNK) load_chunk((chk + 2) % 3, (chk + 2) * SCAN_T);
        else                  cpa_commit();
        cpa_wait1();          // ensure chunk chk+1 resident
        __syncthreads();      // visibility + retire-readers fence (one barrier/chunk)
        buf = (buf + 1) % 3;
    }
}

// ---------------- launch ----------------
extern "C" void kernel_launch(void* const* d_in, const int* in_sizes, int n_in,
                              void* d_out, int out_size)
{
    const float* hidden = (const float*)d_in[0];
    const float* W_in   = (const float*)d_in[1];
    const float* W_out  = (const float*)d_in[2];
    const float* cw_f   = (const float*)d_in[3];
    const float* cb_f   = (const float*)d_in[4];
    const float* Wx_f   = (const float*)d_in[5];
    const float* Wdt_f  = (const float*)d_in[6];
    const float* bdt_f  = (const float*)d_in[7];
    const float* Alog_f = (const float*)d_in[8];
    const float* D_f    = (const float*)d_in[9];
    const float* cw_r   = (const float*)d_in[10];
    const float* cb_r   = (const float*)d_in[11];
    const float* Wx_r   = (const float*)d_in[12];
    const float* Wdt_r  = (const float*)d_in[13];
    const float* bdt_r  = (const float*)d_in[14];
    const float* Alog_r = (const float*)d_in[15];
    const float* D_r    = (const float*)d_in[16];
    float* out = (float*)d_out;

    float* xz;      cudaGetSymbolAddress((void**)&xz,      g_xz);
    float* xc;      cudaGetSymbolAddress((void**)&xc,      g_xc);
    float* xdbl;    cudaGetSymbolAddress((void**)&xdbl,    g_xdbl);
    float* xdbl_tf; cudaGetSymbolAddress((void**)&xdbl_tf, g_xdbl_tf);
    float* dtb;     cudaGetSymbolAddress((void**)&dtb,     g_dt);
    float* yb;      cudaGetSymbolAddress((void**)&yb,      g_y);
    float* hid_tf;  cudaGetSymbolAddress((void**)&hid_tf,  g_hid_tf);
    float* Win_tf;  cudaGetSymbolAddress((void**)&Win_tf,  g_Win_tf);
    float* Wx_tf;   cudaGetSymbolAddress((void**)&Wx_tf,   g_Wx_tf);
    float* Wdt_tf;  cudaGetSymbolAddress((void**)&Wdt_tf,  g_Wdt_tf);
    float* Wout_tf; cudaGetSymbolAddress((void**)&Wout_tf, g_Wout_tf);

    // 0) ONE fused pre-rounding launch (launch #0)
    {
        constexpr int TOT4 = (NR * DM + 2 * DI * DM + 2 * 64 * DI + 2 * DI * DTR + DM * DI) / 4;
        round_all_kernel<<<(TOT4 + 255) / 256, 256>>>(hidden, W_in, W_out,
                                                      Wx_f, Wx_r, Wdt_f, Wdt_r);
    }

    // 1) xz = hidden @ W_in^T   (launch #1)
    {
        dim3 grid((2 * DI) / 128, NR / 128, 1);
        gemm_tf32<128, 0, 0, 0, 0><<<grid, 256>>>(hid_tf, nullptr, DM, Win_tf, nullptr, xz,
                                                  NR, 2 * DI, DM, nullptr, nullptr, 0, 0, nullptr);
    }

    // 2) conv + silu (launch #2)
    {
        int total = 2 * NR * DI;
        conv_silu_kernel<<<(total + 255) / 256, 256>>>(cw_f, cb_f, cw_r, cb_r);
    }

    // 3) x_dbl = xc @ W_x^T  (launch #3; dirs batched on z; DUAL store)
    {
        dim3 grid(1, NR / 128, 2);
        gemm_tf32<64, 0, 0, 1, 1><<<grid, 256>>>(xc, nullptr, DI, Wx_tf, Wx_tf + 64 * DI, xdbl,
                                                 NR, 64, DI, nullptr, nullptr,
                                                 (long)NR * DI, (long)NR * 64, xdbl_tf);
    }

    // 4) dt = softplus(dt_r @ W_dt^T + b_dt)  (launch #4)
    {
        dim3 grid(DI / 128, NR / 128, 2);
        gemm_tf32<128, 1, 0, 0, 0><<<grid, 256>>>(xdbl_tf, nullptr, 64, Wdt_tf, Wdt_tf + DI * DTR, dtb,
                                                  NR, DI, DTR, bdt_f, bdt_r,
                                                  (long)NR * 64, (long)NR * DI, nullptr);
    }

    // 5) selective scan (launch #5 -> profiled by ncu -s 5)
    scan_kernel<<<256, 256>>>(Alog_f, D_f, Alog_r, D_r);

    // 6+7) out = (y_fwd + reverse(y_rev)) @ W_out^T  (launch #6)
    {
        dim3 grid(DM / 128, NR / 128, 1);
        gemm_tf32<128, 0, 1, 1, 0><<<grid, 256>>>(yb, yb + (size_t)NR * DI, DI, Wout_tf, nullptr, out,
                                                  NR, DM, DI, nullptr, nullptr, 0, 0, nullptr);
    }
}